// round 12
// baseline (speedup 1.0000x reference)
#include <cuda_runtime.h>
#include <cstdint>

#define NB 32
#define NT 4096
#define ND 256
#define NK 1024
#define TS_INT 4104        // token stride of intermediate activation buffers

// ---------------- scratch (static device globals; no allocation) ----------------
__device__ float  g_bufA[(size_t)NB * TS_INT * ND];
__device__ float  g_bufB[(size_t)NB * TS_INT * ND];
__device__ float  g_whi[(size_t)ND * 1024];     // weights (conv) / codebook hi (vq)
__device__ float  g_wlo[(size_t)ND * 1024];
__device__ double g_sum[ND];
__device__ double g_sumsq[ND];
__device__ float  g_scale[ND];
__device__ float  g_shift[ND];
__device__ float  g_cnorm[NK];
__device__ float  g_cnt[NK];
__device__ float  g_sumcur[(size_t)NK * ND];
__device__ float  g_n;
__device__ int    g_ids[(size_t)NB * NT];

// ---------------- helpers --------------------------------------------------------
__device__ __forceinline__ uint32_t smem_u32(const void* p) {
    uint32_t a;
    asm("{ .reg .u64 t; cvta.to.shared.u64 t, %1; cvt.u32.u64 %0, t; }" : "=r"(a) : "l"(p));
    return a;
}
__device__ __forceinline__ float tf32r(float x) {
    float r;
    asm("cvt.rna.tf32.f32 %0, %1;" : "=f"(r) : "f"(x));
    return r;
}
__device__ __forceinline__ uint32_t swz(uint32_t off) { return off ^ ((off >> 3) & 0x70); }

__device__ __forceinline__ void ldm_x4(uint32_t& r0, uint32_t& r1, uint32_t& r2, uint32_t& r3, uint32_t a) {
    asm volatile("ldmatrix.sync.aligned.m8n8.x4.shared.b16 {%0,%1,%2,%3}, [%4];"
                 : "=r"(r0), "=r"(r1), "=r"(r2), "=r"(r3) : "r"(a));
}
__device__ __forceinline__ void mma8(float* c, const uint32_t* a, const uint32_t* b) {
    asm volatile("mma.sync.aligned.m16n8k8.row.col.f32.tf32.tf32.f32 "
        "{%0,%1,%2,%3}, {%4,%5,%6,%7}, {%8,%9}, {%0,%1,%2,%3};"
        : "+f"(c[0]), "+f"(c[1]), "+f"(c[2]), "+f"(c[3])
        : "r"(a[0]), "r"(a[1]), "r"(a[2]), "r"(a[3]), "r"(b[0]), "r"(b[1]));
}
#define CP_ASYNC16(dst, src) asm volatile("cp.async.cg.shared.global [%0], [%1], 16;" :: "r"(dst), "l"(src))
#define CP_COMMIT()  asm volatile("cp.async.commit_group;" ::: "memory")
#define CP_WAIT0()   asm volatile("cp.async.wait_group 0;" ::: "memory")

// order-preserving float -> u32 map (finite inputs)
__device__ __forceinline__ uint32_t fbits_ord(float f) {
    uint32_t u = __float_as_uint(f);
    return (u & 0x80000000u) ? ~u : (u | 0x80000000u);
}

// conv smem stage (64-oc tile): A_hi[64 x 128B] | A_lo | B_hi[67+ x 32B] | B_lo
#define O_ALO 8192
#define O_BHI 16384
#define O_BLO (16384 + 2304)
#define STAGE 21504                          // 21 KB, 1024-aligned
#define O_STAT (2 * STAGE)
#define SMEM_MMA (O_STAT + 2048)

// vq smem: z-cache hi[8 chunks][64 rows x 128B] (64KB) | z lo (64KB) | 2 B stages | red
#define VQ_ZLO 65536
#define VQ_B   131072
#define VQ_BST 16384                         // per stage: cb hi 8KB + cb lo 8KB
#define VQ_RED (131072 + 2 * VQ_BST)
#define SMEM_VQ (VQ_RED + 2048)

// ---------------- weight split + permute prep (per conv layer) ------------------
__global__ void wsplit_kernel(const float* __restrict__ w)
{
    int i = blockIdx.x * 256 + threadIdx.x;      // 65536 = (oc, ch)
    int oc = i >> 8, ch = i & 255;
    float4 v = *(const float4*)&w[(size_t)oc * 1024 + ch * 4];
    size_t base = (size_t)oc * 1024 + (ch >> 3) * 32 + (ch & 7);
#pragma unroll
    for (int kk = 0; kk < 4; kk++) {
        float x = (&v.x)[kk];
        float hi = tf32r(x);
        g_whi[base + kk * 8] = hi;
        g_wlo[base + kk * 8] = tf32r(x - hi);
    }
}

// ---------------- plain hi/lo splits for VQ (z and codebook, row-major) ---------
__global__ void zsplit_kernel(const float* __restrict__ ze)
{
    size_t i = (size_t)blockIdx.x * 256 + threadIdx.x;   // float4 index
    float4 v = ((const float4*)ze)[i];
    float4 hi, lo;
    hi.x = tf32r(v.x); lo.x = tf32r(v.x - hi.x);
    hi.y = tf32r(v.y); lo.y = tf32r(v.y - hi.y);
    hi.z = tf32r(v.z); lo.z = tf32r(v.z - hi.z);
    hi.w = tf32r(v.w); lo.w = tf32r(v.w - hi.w);
    ((float4*)g_bufA)[i] = hi;
    ((float4*)g_bufB)[i] = lo;
}

__global__ void csplit_kernel(const float* __restrict__ cb)
{
    size_t i = (size_t)blockIdx.x * 256 + threadIdx.x;   // float4 index, 65536 total
    float4 v = ((const float4*)cb)[i];
    float4 hi, lo;
    hi.x = tf32r(v.x); lo.x = tf32r(v.x - hi.x);
    hi.y = tf32r(v.y); lo.y = tf32r(v.y - hi.y);
    hi.z = tf32r(v.z); lo.z = tf32r(v.z - hi.z);
    hi.w = tf32r(v.w); lo.w = tf32r(v.w - hi.w);
    ((float4*)g_whi)[i] = hi;
    ((float4*)g_wlo)[i] = lo;
}

// ============ conv D->D: mma.sync tf32 3x-split, 3 CTAs/SM ======================
// CTA tile: 64 oc x 64 tok, 8 warps of 16x32. K = 32 chunks of (8 ch x 4 taps).
__global__ __launch_bounds__(256, 3) void convmma_kernel(
    const float* __restrict__ in, const float* __restrict__ bias,
    float* __restrict__ out, int Lin, int Lout, int pad, int tstride, int do_stats)
{
    extern __shared__ __align__(1024) char smem[];
    const int tid = threadIdx.x;
    const int wid = tid >> 5, lane = tid & 31;
    const int b = blockIdx.z, oc0 = blockIdx.y * 64, t0 = blockIdx.x * 64;
    const int ocw = (wid & 3) * 16;          // warp oc base within CTA tile
    const int tokw = (wid >> 2) * 32;        // warp tok base within CTA tile

    const uint32_t sb = smem_u32(smem);
    const float* xb = in + (size_t)b * TS_INT * ND;

    // A fragment base (single m-tile of 16 oc rows)
    uint32_t abase;
    {
        int ar = ocw + (lane & 7) + ((lane >> 3) & 1) * 8;
        int aq = (lane >> 4) & 1;
        abase = (uint32_t)(ar * 128 + ((aq * 16) ^ ((ar & 7) << 4)));
    }
    // B paired-x4 per-lane row base
    const int brow0 = tokw + (lane & 7) + (((lane >> 4) & 1) << 3);
    const uint32_t bcol = (uint32_t)(((lane >> 3) & 1) << 4);

    float C[4][4];
#pragma unroll
    for (int nt = 0; nt < 4; nt++)
#pragma unroll
        for (int q = 0; q < 4; q++) C[nt][q] = 0.f;

    // ---- B prefetch state: threads 0..133 -> (token j = tid>>1, seg h = tid&1) --
    const int jj = tid >> 1, hh = tid & 1;
    const bool bact = (tid < 134);               // rows 0..66 (64 + 3 halo)
    float4 bpre0, spre, hpre;

    // ---- prologue: stage 0 (A: 64 rows hi + 64 rows lo = 1024 float4) ----------
    {
        const float* whp = g_whi + (size_t)oc0 * 1024;
        const float* wlp = g_wlo + (size_t)oc0 * 1024;
#pragma unroll
        for (int it = 0; it < 4; it++) {
            int idx = tid + it * 256, r = idx >> 3, ql = idx & 7, rr = r & 63;
            const float* src = ((r < 64) ? whp : wlp) + (size_t)rr * 1024 + ql * 4;
            uint32_t dst = sb + ((r < 64) ? 0u : (uint32_t)O_ALO) + swz((uint32_t)(rr * 128 + ql * 16));
            CP_ASYNC16(dst, src);
        }
        CP_COMMIT();
        if (bact) {
            int ti = t0 - pad + jj;
            bpre0 = ((unsigned)ti < (unsigned)Lin) ? *(const float4*)&xb[(size_t)ti * ND + hh * 4]
                                                   : make_float4(0.f, 0.f, 0.f, 0.f);
            spre = *(const float4*)&g_scale[hh * 4];
            hpre = *(const float4*)&g_shift[hh * 4];
        }
    }

    for (int cc = 0; cc < 32; cc++) {
        const uint32_t su = sb + (cc & 1) * STAGE;
        char* st = smem + (cc & 1) * STAGE;

        CP_WAIT0();
        // ---- STS B from prefetch regs (BN+ReLU+split at store time) -----------
        if (bact) {
            int ti = t0 - pad + jj;
            bool ok = (unsigned)ti < (unsigned)Lin;
            float4 hi4, lo4;
#pragma unroll
            for (int q = 0; q < 4; q++) {
                float v = ok ? fmaxf(fmaf((&bpre0.x)[q], (&spre.x)[q], (&hpre.x)[q]), 0.f) : 0.f;
                float h = tf32r(v);
                (&hi4.x)[q] = h; (&lo4.x)[q] = tf32r(v - h);
            }
            uint32_t byte = (uint32_t)(jj * 32 + hh * 16) ^ ((uint32_t)(jj & 4) << 2);
            *(float4*)(st + O_BHI + byte) = hi4;
            *(float4*)(st + O_BLO + byte) = lo4;
        }
        __syncthreads();      // single barrier per chunk

        // ---- prefetch chunk cc+1 (A via cp.async, B via regs) ------------------
        if (cc + 1 < 32) {
            const float* whp = g_whi + (size_t)oc0 * 1024 + (cc + 1) * 32;
            const float* wlp = g_wlo + (size_t)oc0 * 1024 + (cc + 1) * 32;
            uint32_t sd = sb + ((cc + 1) & 1) * STAGE;
#pragma unroll
            for (int it = 0; it < 4; it++) {
                int idx = tid + it * 256, r = idx >> 3, ql = idx & 7, rr = r & 63;
                const float* src = ((r < 64) ? whp : wlp) + (size_t)rr * 1024 + ql * 4;
                uint32_t dst = sd + ((r < 64) ? 0u : (uint32_t)O_ALO) + swz((uint32_t)(rr * 128 + ql * 16));
                CP_ASYNC16(dst, src);
            }
            CP_COMMIT();
            if (bact) {
                const int ch0 = (cc + 1) * 8;
                int ti = t0 - pad + jj;
                bpre0 = ((unsigned)ti < (unsigned)Lin) ? *(const float4*)&xb[(size_t)ti * ND + ch0 + hh * 4]
                                                       : make_float4(0.f, 0.f, 0.f, 0.f);
                spre = *(const float4*)&g_scale[ch0 + hh * 4];
                hpre = *(const float4*)&g_shift[ch0 + hh * 4];
            }
        }

        // ---- mma on chunk cc: paired-x4 B loads, deferred A_lo -----------------
#pragma unroll
        for (int ks = 0; ks < 4; ks++) {
            uint32_t bh[4][2], bl[4][2], ah[4], al[4];
#pragma unroll
            for (int p = 0; p < 2; p++) {
                int r = brow0 + p * 16 + ks;
                uint32_t byte = ((uint32_t)(r * 32) + bcol) ^ ((uint32_t)(r & 4) << 2);
                uint32_t ad = su + O_BHI + byte;
                ldm_x4(bh[2 * p][0], bh[2 * p][1], bh[2 * p + 1][0], bh[2 * p + 1][1], ad);
                ldm_x4(bl[2 * p][0], bl[2 * p][1], bl[2 * p + 1][0], bl[2 * p + 1][1],
                       ad + (O_BLO - O_BHI));
            }
            {
                uint32_t ad = su + (abase ^ (uint32_t)(ks << 5));
                ldm_x4(ah[0], ah[1], ah[2], ah[3], ad);
            }
            // pass 1: hi*hi
#pragma unroll
            for (int nt = 0; nt < 4; nt++) mma8(C[nt], ah, bh[nt]);
            // pass 2: hi*lo
#pragma unroll
            for (int nt = 0; nt < 4; nt++) mma8(C[nt], ah, bl[nt]);
            // A lo (deferred)
            {
                uint32_t ad = su + (abase ^ (uint32_t)(ks << 5)) + O_ALO;
                ldm_x4(al[0], al[1], al[2], al[3], ad);
            }
            // pass 3: lo*hi
#pragma unroll
            for (int nt = 0; nt < 4; nt++) mma8(C[nt], al, bh[nt]);
        }
    }
    __syncthreads();

    // ---- epilogue: bias + BN stats + smem transpose + coalesced store ----------
    double* ssumS = (double*)(smem + O_STAT);
    double* ssqS  = (double*)(smem + O_STAT + 512);
    if (tid < 64) { ssumS[tid] = 0.0; ssqS[tid] = 0.0; }
    float* eb = (float*)smem;                 // [64 tok][68 oc]
    __syncthreads();

#pragma unroll
    for (int h = 0; h < 2; h++) {
        int ocl = ocw + (lane >> 2) + h * 8;
        float bv = bias[oc0 + ocl];
        double s = 0.0, q = 0.0;
#pragma unroll
        for (int nt = 0; nt < 4; nt++) {
#pragma unroll
            for (int p = 0; p < 2; p++) {
                int n = tokw + nt * 8 + (lane & 3) * 2 + p;
                float v = C[nt][h * 2 + p] + bv;
                eb[n * 68 + ocl] = v;
                if (do_stats && (t0 + n < Lout)) { double d = (double)v; s += d; q += d * d; }
            }
        }
        if (do_stats) { atomicAdd(&ssumS[ocl], s); atomicAdd(&ssqS[ocl], q); }
    }
    __syncthreads();

    for (int idx = tid; idx < 1024; idx += 256) {
        int r = idx >> 4, ql = idx & 15;
        if (t0 + r < Lout)
            *(float4*)&out[((size_t)b * tstride + t0 + r) * ND + oc0 + ql * 4] =
                *(float4*)&eb[r * 68 + ql * 4];
    }
    if (do_stats && tid < 64) {
        atomicAdd(&g_sum[oc0 + tid], ssumS[tid]);
        atomicAdd(&g_sumsq[oc0 + tid], ssqS[tid]);
    }
}

// ---------------- layer 1: conv 12 -> 256, k=4, pad=2 (scalar; tiny K) ----------
__global__ __launch_bounds__(256) void conv1_kernel(
    const float* __restrict__ x, const float* __restrict__ w,
    const float* __restrict__ bias, float* __restrict__ out)
{
    __shared__ float in_s[12][68];
    __shared__ float w_s[64][49];
    __shared__ float o_s[64][65];
    __shared__ double ssum[64], ssq[64];

    const int tid = threadIdx.x;
    const int b = blockIdx.z, oc0 = blockIdx.y * 64, t0 = blockIdx.x * 64;
    const int ocl = tid & 63, tg = tid >> 6, tbase = tg * 16;
    const int Lout = 4097;

    for (int idx = tid; idx < 12 * 67; idx += 256) {
        int j = idx / 12, c = idx - j * 12;
        int ip = t0 - 2 + j;
        in_s[c][j] = ((unsigned)ip < 4096u) ? x[((size_t)b * NT + ip) * 12 + c] : 0.f;
    }
    for (int idx = tid; idx < 64 * 48; idx += 256) {
        int oc = idx / 48, r = idx - oc * 48;
        w_s[oc][r] = w[(size_t)(oc0 + oc) * 48 + r];
    }
    __syncthreads();

    float acc[16];
#pragma unroll
    for (int u = 0; u < 16; u++) acc[u] = 0.f;
#pragma unroll
    for (int c = 0; c < 12; c++) {
        float v[19];
#pragma unroll
        for (int u = 0; u < 19; u++) v[u] = in_s[c][tbase + u];
        float w0 = w_s[ocl][c * 4 + 0], w1 = w_s[ocl][c * 4 + 1];
        float w2 = w_s[ocl][c * 4 + 2], w3 = w_s[ocl][c * 4 + 3];
#pragma unroll
        for (int u = 0; u < 16; u++)
            acc[u] = fmaf(w3, v[u + 3], fmaf(w2, v[u + 2], fmaf(w1, v[u + 1], fmaf(w0, v[u], acc[u]))));
    }
    const float bv = bias[oc0 + ocl];
#pragma unroll
    for (int u = 0; u < 16; u++) acc[u] += bv;

    {
        double s = 0.0, q = 0.0;
#pragma unroll
        for (int u = 0; u < 16; u++)
            if (t0 + tbase + u < Lout) { double a = (double)acc[u]; s += a; q += a * a; }
        __syncthreads();
        if (tid < 64) { ssum[tid] = 0.0; ssq[tid] = 0.0; }
        __syncthreads();
        atomicAdd(&ssum[ocl], s);
        atomicAdd(&ssq[ocl], q);
        __syncthreads();
        if (tid < 64) {
            atomicAdd(&g_sum[oc0 + tid], ssum[tid]);
            atomicAdd(&g_sumsq[oc0 + tid], ssq[tid]);
        }
    }

    __syncthreads();
#pragma unroll
    for (int u = 0; u < 16; u++) o_s[ocl][tbase + u] = acc[u];
    __syncthreads();
    float* ob = out + ((size_t)b * TS_INT + t0) * ND + oc0;
    for (int idx = tid; idx < 4096; idx += 256) {
        int t = idx >> 6, oc = idx & 63;
        if (t0 + t < Lout) ob[(size_t)t * ND + oc] = o_s[oc][t];
    }
}

// ---------------- BN stats -> scale/shift for next layer; resets stats ----------
__global__ void scaleshift_kernel(const float* __restrict__ g, const float* __restrict__ be, double N)
{
    int c = threadIdx.x;
    double m = g_sum[c] / N;
    double var = g_sumsq[c] / N - m * m;
    double r = 1.0 / sqrt(var + 1e-5);
    double sc = (double)g[c] * r;
    g_scale[c] = (float)sc;
    g_shift[c] = (float)((double)be[c] - m * sc);
    g_sum[c] = 0.0;
    g_sumsq[c] = 0.0;
}

// ---------------- ||codebook_k||^2 (exact fp32) ---------------------------------
__global__ void cnorm_kernel(const float* __restrict__ cb)
{
    int gw = (blockIdx.x * 256 + threadIdx.x) >> 5;
    int lane = threadIdx.x & 31;
    float s = 0.f;
    const float* row = cb + (size_t)gw * ND;
    for (int d = lane; d < ND; d += 32) { float v = row[d]; s = fmaf(v, v, s); }
#pragma unroll
    for (int off = 16; off; off >>= 1) s += __shfl_xor_sync(0xffffffffu, s, off);
    if (lane == 0) g_cnorm[gw] = s;
}

// ============ VQ argmin as mma.sync tf32 3x-split GEMM (round-11, unchanged) ====
__global__ __launch_bounds__(256, 1) void vqmma_kernel(int* __restrict__ ids)
{
    extern __shared__ __align__(1024) char smem[];
    const int tid = threadIdx.x;
    const int wid = tid >> 5, lane = tid & 31;
    const int tok0 = blockIdx.x * 64;
    const int tokw = (wid >> 2) * 32;
    const int cw = (wid & 3) * 16;

    const uint32_t sb = smem_u32(smem);

    {
        const float* zhi = g_bufA;
        const float* zlo = g_bufB;
#pragma unroll
        for (int it = 0; it < 32; it++) {
            int idx = tid + it * 256;
            int q = idx & 7, r = (idx >> 3) & 63, kc = (idx >> 9) & 7, half = idx >> 12;
            const float* src = (half ? zlo : zhi) + ((size_t)(tok0 + r) * 256 + kc * 32 + q * 4);
            uint32_t dst = sb + half * VQ_ZLO + kc * 8192 + swz((uint32_t)(r * 128 + q * 16));
            CP_ASYNC16(dst, src);
        }
        CP_COMMIT();
    }
    {
#pragma unroll
        for (int it = 0; it < 4; it++) {
            int idx = tid + it * 256;
            int q = idx & 7, r = (idx >> 3) & 63, half = idx >> 9;
            const float* src = (half ? g_wlo : g_whi) + ((size_t)r * 256 + q * 4);
            uint32_t dst = sb + VQ_B + half * 8192 + swz((uint32_t)(r * 128 + q * 16));
            CP_ASYNC16(dst, src);
        }
        CP_COMMIT();
    }

    uint32_t abase[2];
    {
        int ar = tokw + (lane & 7) + ((lane >> 3) & 1) * 8;
        int aq = (lane >> 4) & 1;
#pragma unroll
        for (int mt = 0; mt < 2; mt++) {
            int r = ar + mt * 16;
            abase[mt] = (uint32_t)(r * 128 + ((aq * 16) ^ ((r & 7) << 4)));
        }
    }
    const int brow = cw + (lane & 7) + (((lane >> 4) & 1) << 3);
    const uint32_t bcol = (uint32_t)(((lane >> 3) & 1) << 4);

    unsigned long long best[4];
#pragma unroll
    for (int i = 0; i < 4; i++) best[i] = ~0ull;

    float C[2][2][4];

    for (int s = 0; s < 128; s++) {
        const int ct = s >> 3, kc = s & 7;
        const uint32_t bst = sb + VQ_B + (s & 1) * VQ_BST;

        CP_WAIT0();
        __syncthreads();

        if (s + 1 < 128) {
            const int nct = (s + 1) >> 3, nkc = (s + 1) & 7;
            uint32_t sd = sb + VQ_B + ((s + 1) & 1) * VQ_BST;
#pragma unroll
            for (int it = 0; it < 4; it++) {
                int idx = tid + it * 256;
                int q = idx & 7, r = (idx >> 3) & 63, half = idx >> 9;
                const float* src = (half ? g_wlo : g_whi) + ((size_t)(nct * 64 + r) * 256 + nkc * 32 + q * 4);
                uint32_t dst = sd + half * 8192 + swz((uint32_t)(r * 128 + q * 16));
                CP_ASYNC16(dst, src);
            }
            CP_COMMIT();
        }

        if (kc == 0) {
#pragma unroll
            for (int mt = 0; mt < 2; mt++)
#pragma unroll
                for (int nt = 0; nt < 2; nt++)
#pragma unroll
                    for (int q = 0; q < 4; q++) C[mt][nt][q] = 0.f;
        }

        const uint32_t za = sb + kc * 8192;
#pragma unroll
        for (int ks = 0; ks < 4; ks++) {
            uint32_t bh[2][2], bl[2][2], ah[2][4], al[2][4];
            {
                uint32_t byte = (uint32_t)(brow * 128) + (((uint32_t)(ks * 32) + bcol) ^ ((uint32_t)(brow & 7) << 4));
                uint32_t ad = bst + byte;
                ldm_x4(bh[0][0], bh[0][1], bh[1][0], bh[1][1], ad);
                ldm_x4(bl[0][0], bl[0][1], bl[1][0], bl[1][1], ad + 8192);
            }
#pragma unroll
            for (int mt = 0; mt < 2; mt++) {
                uint32_t ad = za + (abase[mt] ^ (uint32_t)(ks << 5));
                ldm_x4(ah[mt][0], ah[mt][1], ah[mt][2], ah[mt][3], ad);
            }
#pragma unroll
            for (int mt = 0; mt < 2; mt++)
#pragma unroll
                for (int nt = 0; nt < 2; nt++) mma8(C[mt][nt], ah[mt], bh[nt]);
#pragma unroll
            for (int mt = 0; mt < 2; mt++)
#pragma unroll
                for (int nt = 0; nt < 2; nt++) mma8(C[mt][nt], ah[mt], bl[nt]);
#pragma unroll
            for (int mt = 0; mt < 2; mt++) {
                uint32_t ad = za + VQ_ZLO + (abase[mt] ^ (uint32_t)(ks << 5));
                ldm_x4(al[mt][0], al[mt][1], al[mt][2], al[mt][3], ad);
            }
#pragma unroll
            for (int mt = 0; mt < 2; mt++)
#pragma unroll
                for (int nt = 0; nt < 2; nt++) mma8(C[mt][nt], al[mt], bh[nt]);
        }

        if (kc == 7) {
#pragma unroll
            for (int mt = 0; mt < 2; mt++)
#pragma unroll
                for (int h = 0; h < 2; h++) {
#pragma unroll
                    for (int nt = 0; nt < 2; nt++)
#pragma unroll
                        for (int p = 0; p < 2; p++) {
                            int code = ct * 64 + cw + nt * 8 + (lane & 3) * 2 + p;
                            float dist = fmaf(-2.f, C[mt][nt][h * 2 + p], g_cnorm[code]);
                            unsigned long long cand =
                                ((unsigned long long)fbits_ord(dist) << 32) | (unsigned)code;
                            unsigned long long* bp = &best[mt * 2 + h];
                            if (cand < *bp) *bp = cand;
                        }
                }
        }
    }

#pragma unroll
    for (int off = 1; off <= 2; off <<= 1) {
#pragma unroll
        for (int i = 0; i < 4; i++) {
            unsigned long long o = __shfl_xor_sync(0xffffffffu, best[i], off);
            if (o < best[i]) best[i] = o;
        }
    }
    unsigned long long* red = (unsigned long long*)(smem + VQ_RED);   // [64][4]
    __syncthreads();
    if ((lane & 3) == 0) {
#pragma unroll
        for (int mt = 0; mt < 2; mt++)
#pragma unroll
            for (int h = 0; h < 2; h++) {
                int trow = tokw + mt * 16 + h * 8 + (lane >> 2);
                red[trow * 4 + (wid & 3)] = best[mt * 2 + h];
            }
    }
    __syncthreads();
    if (tid < 64) {
        unsigned long long m = red[tid * 4];
#pragma unroll
        for (int i = 1; i < 4; i++) { unsigned long long o = red[tid * 4 + i]; if (o < m) m = o; }
        ids[tok0 + tid] = (int)(m & 0xFFFFFFFFu);
    }
}

// ---------------- VQ tail: counts + z_q + segment sums --------------------------
__global__ __launch_bounds__(256) void vqtail_kernel(
    const float* __restrict__ ze, const float* __restrict__ cb, float* __restrict__ zq)
{
    __shared__ int sid[64];
    const int tid = threadIdx.x;
    const int tok0 = blockIdx.x * 64;
    if (tid < 64) sid[tid] = g_ids[tok0 + tid];
    __syncthreads();
    if (tid < 64) atomicAdd(&g_cnt[sid[tid]], 1.0f);
    for (int e = tid; e < 64 * ND; e += 256) {
        int r = e >> 8, d = e & 255;
        int code = sid[r];
        size_t gz = (size_t)(tok0 + r) * ND + d;
        float zev = ze[gz];
        float cbv = cb[(size_t)code * ND + d];
        zq[gz] = zev + (cbv - zev);
        atomicAdd(&g_sumcur[(size_t)code * ND + d], zev);
    }
}

// ---------------- EMA epilogue ---------------------------------------------------
__global__ void ema1_kernel(const float* __restrict__ ecs, float* __restrict__ necs)
{
    __shared__ float red[1024];
    int k = threadIdx.x;
    float ne = ecs[k] * 0.99f + 0.01f * g_cnt[k];
    necs[k] = ne;
    g_cnt[k] = 0.f;
    red[k] = ne;
    __syncthreads();
    for (int off = 512; off; off >>= 1) {
        if (k < off) red[k] += red[k + off];
        __syncthreads();
    }
    if (k == 0) g_n = red[0];
}

__global__ void ema2_kernel(const float* __restrict__ ema_w, const float* __restrict__ necs,
                            float* __restrict__ ncb)
{
    int k = blockIdx.x, d = threadIdx.x;
    float n = g_n;
    float smoothed = (necs[k] + 1e-5f) / (n + 1024.f * 1e-5f) * n;
    size_t idx = (size_t)k * ND + d;
    float nw = ema_w[idx] * 0.99f + 0.01f * g_sumcur[idx];
    ncb[idx] = nw / smoothed;
    g_sumcur[idx] = 0.f;
}

// ---------------- host launcher ---------------------------------------------------
extern "C" void kernel_launch(void* const* d_in, const int* in_sizes, int n_in,
                              void* d_out, int out_size)
{
    const float* X = (const float*)d_in[0];
    const float *W[6], *Bi[6], *G[5], *Be[5];

    bool sig = (in_sizes[3] == 256);
    if (!sig) {
        for (int i = 0; i < 6; i++) { W[i] = (const float*)d_in[1 + 2 * i]; Bi[i] = (const float*)d_in[2 + 2 * i]; }
        for (int i = 0; i < 5; i++) { G[i] = (const float*)d_in[13 + 2 * i]; Be[i] = (const float*)d_in[14 + 2 * i]; }
    } else {
        for (int i = 0; i < 5; i++) {
            W[i]  = (const float*)d_in[1 + 4 * i];
            Bi[i] = (const float*)d_in[2 + 4 * i];
            G[i]  = (const float*)d_in[3 + 4 * i];
            Be[i] = (const float*)d_in[4 + 4 * i];
        }
        W[5] = (const float*)d_in[21];
        Bi[5] = (const float*)d_in[22];
    }
    const float* codebook = (const float*)d_in[23];
    const float* ema_w    = (const float*)d_in[24];
    const float* ecs      = (const float*)d_in[25];

    float* out  = (float*)d_out;
    float* ze   = out;
    float* zq   = out + (size_t)33554432;
    float* ncb  = out + (size_t)67108864;
    float* necs = out + (size_t)67371008;

    float *bufA = nullptr, *bufB = nullptr;
    cudaGetSymbolAddress((void**)&bufA, g_bufA);
    cudaGetSymbolAddress((void**)&bufB, g_bufB);
    int* idsp = nullptr;
    cudaGetSymbolAddress((void**)&idsp, g_ids);

    cudaFuncSetAttribute(convmma_kernel, cudaFuncAttributeMaxDynamicSharedMemorySize, SMEM_MMA);
    cudaFuncSetAttribute(vqmma_kernel, cudaFuncAttributeMaxDynamicSharedMemorySize, SMEM_VQ);

    dim3 blk(256);
    conv1_kernel<<<dim3(65, 4, 32), blk>>>(X, W[0], Bi[0], bufA);
    scaleshift_kernel<<<1, 256>>>(G[0], Be[0], (double)(32.0 * 4097.0));
    wsplit_kernel<<<256, 256>>>(W[1]);
    convmma_kernel<<<dim3(64, 4, 32), blk, SMEM_MMA>>>(bufA, Bi[1], bufB, 4097, 4096, 1, TS_INT, 1);
    scaleshift_kernel<<<1, 256>>>(G[1], Be[1], (double)(32.0 * 4096.0));
    wsplit_kernel<<<256, 256>>>(W[2]);
    convmma_kernel<<<dim3(65, 4, 32), blk, SMEM_MMA>>>(bufB, Bi[2], bufA, 4096, 4097, 2, TS_INT, 1);
    scaleshift_kernel<<<1, 256>>>(G[2], Be[2], (double)(32.0 * 4097.0));
    wsplit_kernel<<<256, 256>>>(W[3]);
    convmma_kernel<<<dim3(64, 4, 32), blk, SMEM_MMA>>>(bufA, Bi[3], bufB, 4097, 4096, 1, TS_INT, 1);
    scaleshift_kernel<<<1, 256>>>(G[3], Be[3], (double)(32.0 * 4096.0));
    wsplit_kernel<<<256, 256>>>(W[4]);
    convmma_kernel<<<dim3(65, 4, 32), blk, SMEM_MMA>>>(bufB, Bi[4], bufA, 4096, 4097, 2, TS_INT, 1);
    scaleshift_kernel<<<1, 256>>>(G[4], Be[4], (double)(32.0 * 4097.0));
    wsplit_kernel<<<256, 256>>>(W[5]);
    convmma_kernel<<<dim3(64, 4, 32), blk, SMEM_MMA>>>(bufA, Bi[5], ze, 4097, 4096, 1, 4096, 0);

    // VQ: split z (reusing bufA/bufB) + codebook, tensor argmin, tail epilogue
    zsplit_kernel<<<32768, 256>>>(ze);
    csplit_kernel<<<256, 256>>>(codebook);
    cnorm_kernel<<<128, 256>>>(codebook);
    vqmma_kernel<<<2048, 256, SMEM_VQ>>>(idsp);
    vqtail_kernel<<<2048, 256>>>(ze, codebook, zq);
    ema1_kernel<<<1, 1024>>>(ecs, necs);
    ema2_kernel<<<1024, 256>>>(ema_w, necs, ncb);
}

// round 13
// speedup vs baseline: 1.0879x; 1.0879x over previous
#include <cuda_runtime.h>
#include <cstdint>

#define NB 32
#define NT 4096
#define ND 256
#define NK 1024
#define TS_INT 4104        // token stride of intermediate activation buffers

// ---------------- scratch (static device globals; no allocation) ----------------
__device__ float  g_bufA[(size_t)NB * TS_INT * ND];
__device__ float  g_bufB[(size_t)NB * TS_INT * ND];
__device__ float  g_zhi[(size_t)NB * NT * ND];   // z_e tf32 hi (written by L6 epilogue)
__device__ float  g_zlo[(size_t)NB * NT * ND];   // z_e tf32 lo
__device__ float  g_whi[(size_t)ND * 1024];      // weights (conv) / codebook hi (vq)
__device__ float  g_wlo[(size_t)ND * 1024];
__device__ double g_sum[ND];
__device__ double g_sumsq[ND];
__device__ float  g_scale[ND];
__device__ float  g_shift[ND];
__device__ float  g_cnorm[NK];
__device__ float  g_cnt[NK];
__device__ float  g_sumcur[(size_t)NK * ND];
__device__ float  g_n;
__device__ int    g_ids[(size_t)NB * NT];

// ---------------- helpers --------------------------------------------------------
__device__ __forceinline__ uint32_t smem_u32(const void* p) {
    uint32_t a;
    asm("{ .reg .u64 t; cvta.to.shared.u64 t, %1; cvt.u32.u64 %0, t; }" : "=r"(a) : "l"(p));
    return a;
}
__device__ __forceinline__ float tf32r(float x) {
    float r;
    asm("cvt.rna.tf32.f32 %0, %1;" : "=f"(r) : "f"(x));
    return r;
}
__device__ __forceinline__ uint32_t swz(uint32_t off) { return off ^ ((off >> 3) & 0x70); }

__device__ __forceinline__ void ldm_x4(uint32_t& r0, uint32_t& r1, uint32_t& r2, uint32_t& r3, uint32_t a) {
    asm volatile("ldmatrix.sync.aligned.m8n8.x4.shared.b16 {%0,%1,%2,%3}, [%4];"
                 : "=r"(r0), "=r"(r1), "=r"(r2), "=r"(r3) : "r"(a));
}
__device__ __forceinline__ void mma8(float* c, const uint32_t* a, const uint32_t* b) {
    asm volatile("mma.sync.aligned.m16n8k8.row.col.f32.tf32.tf32.f32 "
        "{%0,%1,%2,%3}, {%4,%5,%6,%7}, {%8,%9}, {%0,%1,%2,%3};"
        : "+f"(c[0]), "+f"(c[1]), "+f"(c[2]), "+f"(c[3])
        : "r"(a[0]), "r"(a[1]), "r"(a[2]), "r"(a[3]), "r"(b[0]), "r"(b[1]));
}
#define CP_ASYNC16(dst, src) asm volatile("cp.async.cg.shared.global [%0], [%1], 16;" :: "r"(dst), "l"(src))
#define CP_COMMIT()  asm volatile("cp.async.commit_group;" ::: "memory")
#define CP_WAIT0()   asm volatile("cp.async.wait_group 0;" ::: "memory")

// order-preserving float -> u32 map (finite inputs)
__device__ __forceinline__ uint32_t fbits_ord(float f) {
    uint32_t u = __float_as_uint(f);
    return (u & 0x80000000u) ? ~u : (u | 0x80000000u);
}

// conv smem stage (round-11 tile): A_hi[128 x 128B] | A_lo | B_hi[72 x 32B] | B_lo
#define O_ALO 16384
#define O_BHI 32768
#define O_BLO (32768 + 2304)
#define STAGE 37888
#define O_STAT (2 * STAGE)
#define SMEM_MMA (O_STAT + 2048)

// vq smem: z-cache hi[8 chunks][64 rows x 128B] (64KB) | z lo (64KB) | 2 B stages | red
#define VQ_ZLO 65536
#define VQ_B   131072
#define VQ_BST 16384
#define VQ_RED (131072 + 2 * VQ_BST)
#define SMEM_VQ (VQ_RED + 2048)

// ---------------- weight split + permute prep (per conv layer) ------------------
__global__ void wsplit_kernel(const float* __restrict__ w)
{
    int i = blockIdx.x * 256 + threadIdx.x;      // 65536 = (oc, ch)
    int oc = i >> 8, ch = i & 255;
    float4 v = *(const float4*)&w[(size_t)oc * 1024 + ch * 4];
    size_t base = (size_t)oc * 1024 + (ch >> 3) * 32 + (ch & 7);
#pragma unroll
    for (int kk = 0; kk < 4; kk++) {
        float x = (&v.x)[kk];
        float hi = tf32r(x);
        g_whi[base + kk * 8] = hi;
        g_wlo[base + kk * 8] = tf32r(x - hi);
    }
}

// ---------------- codebook hi/lo split (row-major) ------------------------------
__global__ void csplit_kernel(const float* __restrict__ cb)
{
    size_t i = (size_t)blockIdx.x * 256 + threadIdx.x;   // float4 index, 65536 total
    float4 v = ((const float4*)cb)[i];
    float4 hi, lo;
    hi.x = tf32r(v.x); lo.x = tf32r(v.x - hi.x);
    hi.y = tf32r(v.y); lo.y = tf32r(v.y - hi.y);
    hi.z = tf32r(v.z); lo.z = tf32r(v.z - hi.z);
    hi.w = tf32r(v.w); lo.w = tf32r(v.w - hi.w);
    ((float4*)g_whi)[i] = hi;
    ((float4*)g_wlo)[i] = lo;
}

// ============ conv D->D: mma.sync tf32 3x-split, 2 CTAs/SM (round-11 tile) ======
// CTA tile: 128 oc x 64 tok, 8 warps of 32x32. K = 32 chunks of (8 ch x 4 taps).
// split_ze: L6 only — also write tf32 hi/lo of the output into g_zhi/g_zlo.
__global__ __launch_bounds__(256, 2) void convmma_kernel(
    const float* __restrict__ in, const float* __restrict__ bias,
    float* __restrict__ out, int Lin, int Lout, int pad, int tstride,
    int do_stats, int split_ze)
{
    extern __shared__ __align__(1024) char smem[];
    const int tid = threadIdx.x;
    const int wid = tid >> 5, lane = tid & 31;
    const int b = blockIdx.z, oc0 = blockIdx.y * 128, t0 = blockIdx.x * 64;
    const int ocw = (wid & 3) * 32;
    const int tokw = (wid >> 2) * 32;

    const uint32_t sb = smem_u32(smem);
    const float* xb = in + (size_t)b * TS_INT * ND;

    uint32_t abase[2];
    {
        int ar = ocw + (lane & 7) + ((lane >> 3) & 1) * 8;
        int aq = (lane >> 4) & 1;
#pragma unroll
        for (int mt = 0; mt < 2; mt++) {
            int r = ar + mt * 16;
            abase[mt] = (uint32_t)(r * 128 + ((aq * 16) ^ ((r & 7) << 4)));
        }
    }
    const int brow0 = tokw + (lane & 7) + (((lane >> 4) & 1) << 3);
    const uint32_t bcol = (uint32_t)(((lane >> 3) & 1) << 4);

    float C[2][4][4];
#pragma unroll
    for (int mt = 0; mt < 2; mt++)
#pragma unroll
        for (int nt = 0; nt < 4; nt++)
#pragma unroll
            for (int q = 0; q < 4; q++) C[mt][nt][q] = 0.f;

    const int jj = tid >> 1, hh = tid & 1;
    const bool bact = (tid < 134);
    float4 bpre0, spre, hpre;

    {
        const float* whp = g_whi + (size_t)oc0 * 1024;
        const float* wlp = g_wlo + (size_t)oc0 * 1024;
#pragma unroll
        for (int it = 0; it < 8; it++) {
            int idx = tid + it * 256, r = idx >> 3, ql = idx & 7, rr = r & 127;
            const float* src = ((r < 128) ? whp : wlp) + (size_t)rr * 1024 + ql * 4;
            uint32_t dst = sb + ((r < 128) ? 0u : (uint32_t)O_ALO) + swz((uint32_t)(rr * 128 + ql * 16));
            CP_ASYNC16(dst, src);
        }
        CP_COMMIT();
        if (bact) {
            int ti = t0 - pad + jj;
            bpre0 = ((unsigned)ti < (unsigned)Lin) ? *(const float4*)&xb[(size_t)ti * ND + hh * 4]
                                                   : make_float4(0.f, 0.f, 0.f, 0.f);
            spre = *(const float4*)&g_scale[hh * 4];
            hpre = *(const float4*)&g_shift[hh * 4];
        }
    }

    for (int cc = 0; cc < 32; cc++) {
        const uint32_t su = sb + (cc & 1) * STAGE;
        char* st = smem + (cc & 1) * STAGE;

        CP_WAIT0();
        if (bact) {
            int ti = t0 - pad + jj;
            bool ok = (unsigned)ti < (unsigned)Lin;
            float4 hi4, lo4;
#pragma unroll
            for (int q = 0; q < 4; q++) {
                float v = ok ? fmaxf(fmaf((&bpre0.x)[q], (&spre.x)[q], (&hpre.x)[q]), 0.f) : 0.f;
                float h = tf32r(v);
                (&hi4.x)[q] = h; (&lo4.x)[q] = tf32r(v - h);
            }
            uint32_t byte = (uint32_t)(jj * 32 + hh * 16) ^ ((uint32_t)(jj & 4) << 2);
            *(float4*)(st + O_BHI + byte) = hi4;
            *(float4*)(st + O_BLO + byte) = lo4;
        }
        __syncthreads();

        if (cc + 1 < 32) {
            const float* whp = g_whi + (size_t)oc0 * 1024 + (cc + 1) * 32;
            const float* wlp = g_wlo + (size_t)oc0 * 1024 + (cc + 1) * 32;
            uint32_t sd = sb + ((cc + 1) & 1) * STAGE;
#pragma unroll
            for (int it = 0; it < 8; it++) {
                int idx = tid + it * 256, r = idx >> 3, ql = idx & 7, rr = r & 127;
                const float* src = ((r < 128) ? whp : wlp) + (size_t)rr * 1024 + ql * 4;
                uint32_t dst = sd + ((r < 128) ? 0u : (uint32_t)O_ALO) + swz((uint32_t)(rr * 128 + ql * 16));
                CP_ASYNC16(dst, src);
            }
            CP_COMMIT();
            if (bact) {
                const int ch0 = (cc + 1) * 8;
                int ti = t0 - pad + jj;
                bpre0 = ((unsigned)ti < (unsigned)Lin) ? *(const float4*)&xb[(size_t)ti * ND + ch0 + hh * 4]
                                                       : make_float4(0.f, 0.f, 0.f, 0.f);
                spre = *(const float4*)&g_scale[ch0 + hh * 4];
                hpre = *(const float4*)&g_shift[ch0 + hh * 4];
            }
        }

#pragma unroll
        for (int ks = 0; ks < 4; ks++) {
            uint32_t bh[4][2], bl[4][2], ah[2][4], al[2][4];
#pragma unroll
            for (int p = 0; p < 2; p++) {
                int r = brow0 + p * 16 + ks;
                uint32_t byte = ((uint32_t)(r * 32) + bcol) ^ ((uint32_t)(r & 4) << 2);
                uint32_t ad = su + O_BHI + byte;
                ldm_x4(bh[2 * p][0], bh[2 * p][1], bh[2 * p + 1][0], bh[2 * p + 1][1], ad);
                ldm_x4(bl[2 * p][0], bl[2 * p][1], bl[2 * p + 1][0], bl[2 * p + 1][1],
                       ad + (O_BLO - O_BHI));
            }
#pragma unroll
            for (int mt = 0; mt < 2; mt++) {
                uint32_t ad = su + (abase[mt] ^ (uint32_t)(ks << 5));
                ldm_x4(ah[mt][0], ah[mt][1], ah[mt][2], ah[mt][3], ad);
            }
#pragma unroll
            for (int mt = 0; mt < 2; mt++)
#pragma unroll
                for (int nt = 0; nt < 4; nt++) mma8(C[mt][nt], ah[mt], bh[nt]);
#pragma unroll
            for (int mt = 0; mt < 2; mt++)
#pragma unroll
                for (int nt = 0; nt < 4; nt++) mma8(C[mt][nt], ah[mt], bl[nt]);
#pragma unroll
            for (int mt = 0; mt < 2; mt++) {
                uint32_t ad = su + (abase[mt] ^ (uint32_t)(ks << 5)) + O_ALO;
                ldm_x4(al[mt][0], al[mt][1], al[mt][2], al[mt][3], ad);
            }
#pragma unroll
            for (int mt = 0; mt < 2; mt++)
#pragma unroll
                for (int nt = 0; nt < 4; nt++) mma8(C[mt][nt], al[mt], bh[nt]);
        }
    }
    __syncthreads();

    // ---- epilogue: bias + BN stats + smem transpose + coalesced store ----------
    double* ssumS = (double*)(smem + O_STAT);
    double* ssqS  = (double*)(smem + O_STAT + 1024);
    if (tid < 128) { ssumS[tid] = 0.0; ssqS[tid] = 0.0; }
    float* eb = (float*)smem;                 // [64 tok][132 oc]
    __syncthreads();

#pragma unroll
    for (int mt = 0; mt < 2; mt++) {
#pragma unroll
        for (int h = 0; h < 2; h++) {
            int ocl = ocw + mt * 16 + (lane >> 2) + h * 8;
            float bv = bias[oc0 + ocl];
            double s = 0.0, q = 0.0;
#pragma unroll
            for (int nt = 0; nt < 4; nt++) {
#pragma unroll
                for (int p = 0; p < 2; p++) {
                    int n = tokw + nt * 8 + (lane & 3) * 2 + p;
                    float v = C[mt][nt][h * 2 + p] + bv;
                    eb[n * 132 + ocl] = v;
                    if (do_stats && (t0 + n < Lout)) { double d = (double)v; s += d; q += d * d; }
                }
            }
            if (do_stats) { atomicAdd(&ssumS[ocl], s); atomicAdd(&ssqS[ocl], q); }
        }
    }
    __syncthreads();

    for (int idx = tid; idx < 2048; idx += 256) {
        int r = idx >> 5, ql = idx & 31;
        if (t0 + r < Lout) {
            float4 v = *(float4*)&eb[r * 132 + ql * 4];
            size_t go = ((size_t)b * tstride + t0 + r) * ND + oc0 + ql * 4;
            *(float4*)&out[go] = v;
            if (split_ze) {
                float4 hi, lo;
                hi.x = tf32r(v.x); lo.x = tf32r(v.x - hi.x);
                hi.y = tf32r(v.y); lo.y = tf32r(v.y - hi.y);
                hi.z = tf32r(v.z); lo.z = tf32r(v.z - hi.z);
                hi.w = tf32r(v.w); lo.w = tf32r(v.w - hi.w);
                size_t zo = ((size_t)b * NT + t0 + r) * ND + oc0 + ql * 4;
                *(float4*)&g_zhi[zo] = hi;
                *(float4*)&g_zlo[zo] = lo;
            }
        }
    }
    if (do_stats && tid < 128) {
        atomicAdd(&g_sum[oc0 + tid], ssumS[tid]);
        atomicAdd(&g_sumsq[oc0 + tid], ssqS[tid]);
    }
}

// ---------------- layer 1: conv 12 -> 256, k=4, pad=2 (scalar; tiny K) ----------
__global__ __launch_bounds__(256) void conv1_kernel(
    const float* __restrict__ x, const float* __restrict__ w,
    const float* __restrict__ bias, float* __restrict__ out)
{
    __shared__ float in_s[12][68];
    __shared__ float w_s[64][49];
    __shared__ float o_s[64][65];
    __shared__ double ssum[64], ssq[64];

    const int tid = threadIdx.x;
    const int b = blockIdx.z, oc0 = blockIdx.y * 64, t0 = blockIdx.x * 64;
    const int ocl = tid & 63, tg = tid >> 6, tbase = tg * 16;
    const int Lout = 4097;

    for (int idx = tid; idx < 12 * 67; idx += 256) {
        int j = idx / 12, c = idx - j * 12;
        int ip = t0 - 2 + j;
        in_s[c][j] = ((unsigned)ip < 4096u) ? x[((size_t)b * NT + ip) * 12 + c] : 0.f;
    }
    for (int idx = tid; idx < 64 * 48; idx += 256) {
        int oc = idx / 48, r = idx - oc * 48;
        w_s[oc][r] = w[(size_t)(oc0 + oc) * 48 + r];
    }
    __syncthreads();

    float acc[16];
#pragma unroll
    for (int u = 0; u < 16; u++) acc[u] = 0.f;
#pragma unroll
    for (int c = 0; c < 12; c++) {
        float v[19];
#pragma unroll
        for (int u = 0; u < 19; u++) v[u] = in_s[c][tbase + u];
        float w0 = w_s[ocl][c * 4 + 0], w1 = w_s[ocl][c * 4 + 1];
        float w2 = w_s[ocl][c * 4 + 2], w3 = w_s[ocl][c * 4 + 3];
#pragma unroll
        for (int u = 0; u < 16; u++)
            acc[u] = fmaf(w3, v[u + 3], fmaf(w2, v[u + 2], fmaf(w1, v[u + 1], fmaf(w0, v[u], acc[u]))));
    }
    const float bv = bias[oc0 + ocl];
#pragma unroll
    for (int u = 0; u < 16; u++) acc[u] += bv;

    {
        double s = 0.0, q = 0.0;
#pragma unroll
        for (int u = 0; u < 16; u++)
            if (t0 + tbase + u < Lout) { double a = (double)acc[u]; s += a; q += a * a; }
        __syncthreads();
        if (tid < 64) { ssum[tid] = 0.0; ssq[tid] = 0.0; }
        __syncthreads();
        atomicAdd(&ssum[ocl], s);
        atomicAdd(&ssq[ocl], q);
        __syncthreads();
        if (tid < 64) {
            atomicAdd(&g_sum[oc0 + tid], ssum[tid]);
            atomicAdd(&g_sumsq[oc0 + tid], ssq[tid]);
        }
    }

    __syncthreads();
#pragma unroll
    for (int u = 0; u < 16; u++) o_s[ocl][tbase + u] = acc[u];
    __syncthreads();
    float* ob = out + ((size_t)b * TS_INT + t0) * ND + oc0;
    for (int idx = tid; idx < 4096; idx += 256) {
        int t = idx >> 6, oc = idx & 63;
        if (t0 + t < Lout) ob[(size_t)t * ND + oc] = o_s[oc][t];
    }
}

// ---------------- BN stats -> scale/shift for next layer; resets stats ----------
__global__ void scaleshift_kernel(const float* __restrict__ g, const float* __restrict__ be, double N)
{
    int c = threadIdx.x;
    double m = g_sum[c] / N;
    double var = g_sumsq[c] / N - m * m;
    double r = 1.0 / sqrt(var + 1e-5);
    double sc = (double)g[c] * r;
    g_scale[c] = (float)sc;
    g_shift[c] = (float)((double)be[c] - m * sc);
    g_sum[c] = 0.0;
    g_sumsq[c] = 0.0;
}

// ---------------- ||codebook_k||^2 (exact fp32) ---------------------------------
__global__ void cnorm_kernel(const float* __restrict__ cb)
{
    int gw = (blockIdx.x * 256 + threadIdx.x) >> 5;
    int lane = threadIdx.x & 31;
    float s = 0.f;
    const float* row = cb + (size_t)gw * ND;
    for (int d = lane; d < ND; d += 32) { float v = row[d]; s = fmaf(v, v, s); }
#pragma unroll
    for (int off = 16; off; off >>= 1) s += __shfl_xor_sync(0xffffffffu, s, off);
    if (lane == 0) g_cnorm[gw] = s;
}

// ============ VQ argmin as mma.sync tf32 3x-split GEMM (round-11, src=g_zhi/lo) =
__global__ __launch_bounds__(256, 1) void vqmma_kernel(int* __restrict__ ids)
{
    extern __shared__ __align__(1024) char smem[];
    const int tid = threadIdx.x;
    const int wid = tid >> 5, lane = tid & 31;
    const int tok0 = blockIdx.x * 64;
    const int tokw = (wid >> 2) * 32;
    const int cw = (wid & 3) * 16;

    const uint32_t sb = smem_u32(smem);

    {
        const float* zhi = g_zhi;
        const float* zlo = g_zlo;
#pragma unroll
        for (int it = 0; it < 32; it++) {
            int idx = tid + it * 256;
            int q = idx & 7, r = (idx >> 3) & 63, kc = (idx >> 9) & 7, half = idx >> 12;
            const float* src = (half ? zlo : zhi) + ((size_t)(tok0 + r) * 256 + kc * 32 + q * 4);
            uint32_t dst = sb + half * VQ_ZLO + kc * 8192 + swz((uint32_t)(r * 128 + q * 16));
            CP_ASYNC16(dst, src);
        }
        CP_COMMIT();
    }
    {
#pragma unroll
        for (int it = 0; it < 4; it++) {
            int idx = tid + it * 256;
            int q = idx & 7, r = (idx >> 3) & 63, half = idx >> 9;
            const float* src = (half ? g_wlo : g_whi) + ((size_t)r * 256 + q * 4);
            uint32_t dst = sb + VQ_B + half * 8192 + swz((uint32_t)(r * 128 + q * 16));
            CP_ASYNC16(dst, src);
        }
        CP_COMMIT();
    }

    uint32_t abase[2];
    {
        int ar = tokw + (lane & 7) + ((lane >> 3) & 1) * 8;
        int aq = (lane >> 4) & 1;
#pragma unroll
        for (int mt = 0; mt < 2; mt++) {
            int r = ar + mt * 16;
            abase[mt] = (uint32_t)(r * 128 + ((aq * 16) ^ ((r & 7) << 4)));
        }
    }
    const int brow = cw + (lane & 7) + (((lane >> 4) & 1) << 3);
    const uint32_t bcol = (uint32_t)(((lane >> 3) & 1) << 4);

    unsigned long long best[4];
#pragma unroll
    for (int i = 0; i < 4; i++) best[i] = ~0ull;

    float C[2][2][4];

    for (int s = 0; s < 128; s++) {
        const int ct = s >> 3, kc = s & 7;
        const uint32_t bst = sb + VQ_B + (s & 1) * VQ_BST;

        CP_WAIT0();
        __syncthreads();

        if (s + 1 < 128) {
            const int nct = (s + 1) >> 3, nkc = (s + 1) & 7;
            uint32_t sd = sb + VQ_B + ((s + 1) & 1) * VQ_BST;
#pragma unroll
            for (int it = 0; it < 4; it++) {
                int idx = tid + it * 256;
                int q = idx & 7, r = (idx >> 3) & 63, half = idx >> 9;
                const float* src = (half ? g_wlo : g_whi) + ((size_t)(nct * 64 + r) * 256 + nkc * 32 + q * 4);
                uint32_t dst = sd + half * 8192 + swz((uint32_t)(r * 128 + q * 16));
                CP_ASYNC16(dst, src);
            }
            CP_COMMIT();
        }

        if (kc == 0) {
#pragma unroll
            for (int mt = 0; mt < 2; mt++)
#pragma unroll
                for (int nt = 0; nt < 2; nt++)
#pragma unroll
                    for (int q = 0; q < 4; q++) C[mt][nt][q] = 0.f;
        }

        const uint32_t za = sb + kc * 8192;
#pragma unroll
        for (int ks = 0; ks < 4; ks++) {
            uint32_t bh[2][2], bl[2][2], ah[2][4], al[2][4];
            {
                uint32_t byte = (uint32_t)(brow * 128) + (((uint32_t)(ks * 32) + bcol) ^ ((uint32_t)(brow & 7) << 4));
                uint32_t ad = bst + byte;
                ldm_x4(bh[0][0], bh[0][1], bh[1][0], bh[1][1], ad);
                ldm_x4(bl[0][0], bl[0][1], bl[1][0], bl[1][1], ad + 8192);
            }
#pragma unroll
            for (int mt = 0; mt < 2; mt++) {
                uint32_t ad = za + (abase[mt] ^ (uint32_t)(ks << 5));
                ldm_x4(ah[mt][0], ah[mt][1], ah[mt][2], ah[mt][3], ad);
            }
#pragma unroll
            for (int mt = 0; mt < 2; mt++)
#pragma unroll
                for (int nt = 0; nt < 2; nt++) mma8(C[mt][nt], ah[mt], bh[nt]);
#pragma unroll
            for (int mt = 0; mt < 2; mt++)
#pragma unroll
                for (int nt = 0; nt < 2; nt++) mma8(C[mt][nt], ah[mt], bl[nt]);
#pragma unroll
            for (int mt = 0; mt < 2; mt++) {
                uint32_t ad = za + VQ_ZLO + (abase[mt] ^ (uint32_t)(ks << 5));
                ldm_x4(al[mt][0], al[mt][1], al[mt][2], al[mt][3], ad);
            }
#pragma unroll
            for (int mt = 0; mt < 2; mt++)
#pragma unroll
                for (int nt = 0; nt < 2; nt++) mma8(C[mt][nt], al[mt], bh[nt]);
        }

        if (kc == 7) {
#pragma unroll
            for (int mt = 0; mt < 2; mt++)
#pragma unroll
                for (int h = 0; h < 2; h++) {
#pragma unroll
                    for (int nt = 0; nt < 2; nt++)
#pragma unroll
                        for (int p = 0; p < 2; p++) {
                            int code = ct * 64 + cw + nt * 8 + (lane & 3) * 2 + p;
                            float dist = fmaf(-2.f, C[mt][nt][h * 2 + p], g_cnorm[code]);
                            unsigned long long cand =
                                ((unsigned long long)fbits_ord(dist) << 32) | (unsigned)code;
                            unsigned long long* bp = &best[mt * 2 + h];
                            if (cand < *bp) *bp = cand;
                        }
                }
        }
    }

#pragma unroll
    for (int off = 1; off <= 2; off <<= 1) {
#pragma unroll
        for (int i = 0; i < 4; i++) {
            unsigned long long o = __shfl_xor_sync(0xffffffffu, best[i], off);
            if (o < best[i]) best[i] = o;
        }
    }
    unsigned long long* red = (unsigned long long*)(smem + VQ_RED);   // [64][4]
    __syncthreads();
    if ((lane & 3) == 0) {
#pragma unroll
        for (int mt = 0; mt < 2; mt++)
#pragma unroll
            for (int h = 0; h < 2; h++) {
                int trow = tokw + mt * 16 + h * 8 + (lane >> 2);
                red[trow * 4 + (wid & 3)] = best[mt * 2 + h];
            }
    }
    __syncthreads();
    if (tid < 64) {
        unsigned long long m = red[tid * 4];
#pragma unroll
        for (int i = 1; i < 4; i++) { unsigned long long o = red[tid * 4 + i]; if (o < m) m = o; }
        ids[tok0 + tid] = (int)(m & 0xFFFFFFFFu);
    }
}

// ---------------- VQ tail: counts + z_q + segment sums --------------------------
__global__ __launch_bounds__(256) void vqtail_kernel(
    const float* __restrict__ ze, const float* __restrict__ cb, float* __restrict__ zq)
{
    __shared__ int sid[64];
    const int tid = threadIdx.x;
    const int tok0 = blockIdx.x * 64;
    if (tid < 64) sid[tid] = g_ids[tok0 + tid];
    __syncthreads();
    if (tid < 64) atomicAdd(&g_cnt[sid[tid]], 1.0f);
    for (int e = tid; e < 64 * ND; e += 256) {
        int r = e >> 8, d = e & 255;
        int code = sid[r];
        size_t gz = (size_t)(tok0 + r) * ND + d;
        float zev = ze[gz];
        float cbv = cb[(size_t)code * ND + d];
        zq[gz] = zev + (cbv - zev);
        atomicAdd(&g_sumcur[(size_t)code * ND + d], zev);
    }
}

// ---------------- EMA epilogue ---------------------------------------------------
__global__ void ema1_kernel(const float* __restrict__ ecs, float* __restrict__ necs)
{
    __shared__ float red[1024];
    int k = threadIdx.x;
    float ne = ecs[k] * 0.99f + 0.01f * g_cnt[k];
    necs[k] = ne;
    g_cnt[k] = 0.f;
    red[k] = ne;
    __syncthreads();
    for (int off = 512; off; off >>= 1) {
        if (k < off) red[k] += red[k + off];
        __syncthreads();
    }
    if (k == 0) g_n = red[0];
}

__global__ void ema2_kernel(const float* __restrict__ ema_w, const float* __restrict__ necs,
                            float* __restrict__ ncb)
{
    int k = blockIdx.x, d = threadIdx.x;
    float n = g_n;
    float smoothed = (necs[k] + 1e-5f) / (n + 1024.f * 1e-5f) * n;
    size_t idx = (size_t)k * ND + d;
    float nw = ema_w[idx] * 0.99f + 0.01f * g_sumcur[idx];
    ncb[idx] = nw / smoothed;
    g_sumcur[idx] = 0.f;
}

// ---------------- host launcher ---------------------------------------------------
extern "C" void kernel_launch(void* const* d_in, const int* in_sizes, int n_in,
                              void* d_out, int out_size)
{
    const float* X = (const float*)d_in[0];
    const float *W[6], *Bi[6], *G[5], *Be[5];

    bool sig = (in_sizes[3] == 256);
    if (!sig) {
        for (int i = 0; i < 6; i++) { W[i] = (const float*)d_in[1 + 2 * i]; Bi[i] = (const float*)d_in[2 + 2 * i]; }
        for (int i = 0; i < 5; i++) { G[i] = (const float*)d_in[13 + 2 * i]; Be[i] = (const float*)d_in[14 + 2 * i]; }
    } else {
        for (int i = 0; i < 5; i++) {
            W[i]  = (const float*)d_in[1 + 4 * i];
            Bi[i] = (const float*)d_in[2 + 4 * i];
            G[i]  = (const float*)d_in[3 + 4 * i];
            Be[i] = (const float*)d_in[4 + 4 * i];
        }
        W[5] = (const float*)d_in[21];
        Bi[5] = (const float*)d_in[22];
    }
    const float* codebook = (const float*)d_in[23];
    const float* ema_w    = (const float*)d_in[24];
    const float* ecs      = (const float*)d_in[25];

    float* out  = (float*)d_out;
    float* ze   = out;
    float* zq   = out + (size_t)33554432;
    float* ncb  = out + (size_t)67108864;
    float* necs = out + (size_t)67371008;

    float *bufA = nullptr, *bufB = nullptr;
    cudaGetSymbolAddress((void**)&bufA, g_bufA);
    cudaGetSymbolAddress((void**)&bufB, g_bufB);
    int* idsp = nullptr;
    cudaGetSymbolAddress((void**)&idsp, g_ids);

    cudaFuncSetAttribute(convmma_kernel, cudaFuncAttributeMaxDynamicSharedMemorySize, SMEM_MMA);
    cudaFuncSetAttribute(vqmma_kernel, cudaFuncAttributeMaxDynamicSharedMemorySize, SMEM_VQ);

    dim3 blk(256);
    conv1_kernel<<<dim3(65, 4, 32), blk>>>(X, W[0], Bi[0], bufA);
    scaleshift_kernel<<<1, 256>>>(G[0], Be[0], (double)(32.0 * 4097.0));
    wsplit_kernel<<<256, 256>>>(W[1]);
    convmma_kernel<<<dim3(64, 2, 32), blk, SMEM_MMA>>>(bufA, Bi[1], bufB, 4097, 4096, 1, TS_INT, 1, 0);
    scaleshift_kernel<<<1, 256>>>(G[1], Be[1], (double)(32.0 * 4096.0));
    wsplit_kernel<<<256, 256>>>(W[2]);
    convmma_kernel<<<dim3(65, 2, 32), blk, SMEM_MMA>>>(bufB, Bi[2], bufA, 4096, 4097, 2, TS_INT, 1, 0);
    scaleshift_kernel<<<1, 256>>>(G[2], Be[2], (double)(32.0 * 4097.0));
    wsplit_kernel<<<256, 256>>>(W[3]);
    convmma_kernel<<<dim3(64, 2, 32), blk, SMEM_MMA>>>(bufA, Bi[3], bufB, 4097, 4096, 1, TS_INT, 1, 0);
    scaleshift_kernel<<<1, 256>>>(G[3], Be[3], (double)(32.0 * 4096.0));
    wsplit_kernel<<<256, 256>>>(W[4]);
    convmma_kernel<<<dim3(65, 2, 32), blk, SMEM_MMA>>>(bufB, Bi[4], bufA, 4096, 4097, 2, TS_INT, 1, 0);
    scaleshift_kernel<<<1, 256>>>(G[4], Be[4], (double)(32.0 * 4097.0));
    wsplit_kernel<<<256, 256>>>(W[5]);
    // L6: writes z_e AND its tf32 hi/lo split (fused; replaces zsplit kernel)
    convmma_kernel<<<dim3(64, 2, 32), blk, SMEM_MMA>>>(bufA, Bi[5], ze, 4097, 4096, 1, 4096, 0, 1);

    csplit_kernel<<<256, 256>>>(codebook);
    cnorm_kernel<<<128, 256>>>(codebook);
    vqmma_kernel<<<2048, 256, SMEM_VQ>>>(idsp);
    vqtail_kernel<<<2048, 256>>>(ze, codebook, zq);
    ema1_kernel<<<1, 1024>>>(ecs, necs);
    ema2_kernel<<<1024, 256>>>(ema_w, necs, ncb);
}

// round 14
// speedup vs baseline: 1.1098x; 1.0201x over previous
#include <cuda_runtime.h>
#include <cstdint>

#define NB 32
#define NT 4096
#define ND 256
#define NK 1024
#define TS_INT 4104        // token stride of intermediate activation buffers

// ---------------- scratch (static device globals; no allocation) ----------------
__device__ float  g_bufA[(size_t)NB * TS_INT * ND];
__device__ float  g_bufB[(size_t)NB * TS_INT * ND];
__device__ float  g_zhi[(size_t)NB * NT * ND];   // z_e tf32 hi (written by L6 epilogue)
__device__ float  g_zlo[(size_t)NB * NT * ND];   // z_e tf32 lo
__device__ float  g_whi[(size_t)ND * 1024];      // weights (conv) / codebook hi (vq)
__device__ float  g_wlo[(size_t)ND * 1024];
__device__ double g_sum[ND];
__device__ double g_sumsq[ND];
__device__ float  g_scale[ND];
__device__ float  g_shift[ND];
__device__ float  g_cnorm[NK];
__device__ float  g_cnt[NK];
__device__ float  g_sumcur[(size_t)NK * ND];
__device__ float  g_n;
__device__ int    g_ids[(size_t)NB * NT];

// ---------------- helpers --------------------------------------------------------
__device__ __forceinline__ uint32_t smem_u32(const void* p) {
    uint32_t a;
    asm("{ .reg .u64 t; cvta.to.shared.u64 t, %1; cvt.u32.u64 %0, t; }" : "=r"(a) : "l"(p));
    return a;
}
__device__ __forceinline__ float tf32r(float x) {
    float r;
    asm("cvt.rna.tf32.f32 %0, %1;" : "=f"(r) : "f"(x));
    return r;
}
__device__ __forceinline__ uint32_t swz(uint32_t off) { return off ^ ((off >> 3) & 0x70); }

__device__ __forceinline__ void ldm_x4(uint32_t& r0, uint32_t& r1, uint32_t& r2, uint32_t& r3, uint32_t a) {
    asm volatile("ldmatrix.sync.aligned.m8n8.x4.shared.b16 {%0,%1,%2,%3}, [%4];"
                 : "=r"(r0), "=r"(r1), "=r"(r2), "=r"(r3) : "r"(a));
}
__device__ __forceinline__ void mma8(float* c, const uint32_t* a, const uint32_t* b) {
    asm volatile("mma.sync.aligned.m16n8k8.row.col.f32.tf32.tf32.f32 "
        "{%0,%1,%2,%3}, {%4,%5,%6,%7}, {%8,%9}, {%0,%1,%2,%3};"
        : "+f"(c[0]), "+f"(c[1]), "+f"(c[2]), "+f"(c[3])
        : "r"(a[0]), "r"(a[1]), "r"(a[2]), "r"(a[3]), "r"(b[0]), "r"(b[1]));
}
#define CP_ASYNC16(dst, src) asm volatile("cp.async.cg.shared.global [%0], [%1], 16;" :: "r"(dst), "l"(src))
#define CP_COMMIT()  asm volatile("cp.async.commit_group;" ::: "memory")
#define CP_WAIT0()   asm volatile("cp.async.wait_group 0;" ::: "memory")

// order-preserving float -> u32 map (finite inputs)
__device__ __forceinline__ uint32_t fbits_ord(float f) {
    uint32_t u = __float_as_uint(f);
    return (u & 0x80000000u) ? ~u : (u | 0x80000000u);
}

// conv smem stage (64oc x 64tok tile): A_hi[64 x 128B] | A_lo | B_hi[72 x 32B] | B_lo
#define O_ALO 8192
#define O_BHI 16384
#define O_BLO (16384 + 2304)
#define STAGE 21504                           // 21 KB, 1024-aligned
#define O_STAT (2 * STAGE)
#define SMEM_MMA (O_STAT + 2048)

// vq smem: z-cache hi[8 chunks][64 rows x 128B] (64KB) | z lo (64KB) | 2 B stages | red
#define VQ_ZLO 65536
#define VQ_B   131072
#define VQ_BST 16384
#define VQ_RED (131072 + 2 * VQ_BST)
#define SMEM_VQ (VQ_RED + 2048)

// ---------------- weight split + permute prep (per conv layer) ------------------
__global__ void wsplit_kernel(const float* __restrict__ w)
{
    int i = blockIdx.x * 256 + threadIdx.x;      // 65536 = (oc, ch)
    int oc = i >> 8, ch = i & 255;
    float4 v = *(const float4*)&w[(size_t)oc * 1024 + ch * 4];
    size_t base = (size_t)oc * 1024 + (ch >> 3) * 32 + (ch & 7);
#pragma unroll
    for (int kk = 0; kk < 4; kk++) {
        float x = (&v.x)[kk];
        float hi = tf32r(x);
        g_whi[base + kk * 8] = hi;
        g_wlo[base + kk * 8] = tf32r(x - hi);
    }
}

// ---------------- codebook hi/lo split (row-major) ------------------------------
__global__ void csplit_kernel(const float* __restrict__ cb)
{
    size_t i = (size_t)blockIdx.x * 256 + threadIdx.x;   // float4 index, 65536 total
    float4 v = ((const float4*)cb)[i];
    float4 hi, lo;
    hi.x = tf32r(v.x); lo.x = tf32r(v.x - hi.x);
    hi.y = tf32r(v.y); lo.y = tf32r(v.y - hi.y);
    hi.z = tf32r(v.z); lo.z = tf32r(v.z - hi.z);
    hi.w = tf32r(v.w); lo.w = tf32r(v.w - hi.w);
    ((float4*)g_whi)[i] = hi;
    ((float4*)g_wlo)[i] = lo;
}

// ============ conv D->D: mma.sync tf32 3x-split, 4 CTAs/SM ======================
// CTA: 128 threads (4 warps), tile 64 oc x 64 tok, warp tile 32x32 (mt=2, nt=4).
// K = 32 chunks of (8 ch x 4 taps). split_ze: L6 also writes tf32 hi/lo of out.
__global__ __launch_bounds__(128, 4) void convmma_kernel(
    const float* __restrict__ in, const float* __restrict__ bias,
    float* __restrict__ out, int Lin, int Lout, int pad, int tstride,
    int do_stats, int split_ze)
{
    extern __shared__ __align__(1024) char smem[];
    const int tid = threadIdx.x;
    const int wid = tid >> 5, lane = tid & 31;
    const int b = blockIdx.z, oc0 = blockIdx.y * 64, t0 = blockIdx.x * 64;
    const int ocw = (wid & 1) * 32;          // warp oc base within CTA tile
    const int tokw = (wid >> 1) * 32;        // warp tok base within CTA tile

    const uint32_t sb = smem_u32(smem);
    const float* xb = in + (size_t)b * TS_INT * ND;

    uint32_t abase[2];
    {
        int ar = ocw + (lane & 7) + ((lane >> 3) & 1) * 8;
        int aq = (lane >> 4) & 1;
#pragma unroll
        for (int mt = 0; mt < 2; mt++) {
            int r = ar + mt * 16;
            abase[mt] = (uint32_t)(r * 128 + ((aq * 16) ^ ((r & 7) << 4)));
        }
    }
    const int brow0 = tokw + (lane & 7) + (((lane >> 4) & 1) << 3);
    const uint32_t bcol = (uint32_t)(((lane >> 3) & 1) << 4);

    float C[2][4][4];
#pragma unroll
    for (int mt = 0; mt < 2; mt++)
#pragma unroll
        for (int nt = 0; nt < 4; nt++)
#pragma unroll
            for (int q = 0; q < 4; q++) C[mt][nt][q] = 0.f;

    // B producer: 128 threads cover rows 0..63 (j = tid>>1, seg h = tid&1);
    // halo rows 64..66 handled by threads 0..5 via jx.
    const int jj = tid >> 1, hh = tid & 1;
    const int jx = 64 + (tid >> 1);
    float4 bpre0, bpre1, spre, hpre;

    // ---- prologue: stage 0 (A: 64 rows hi + 64 lo = 1024 float4) ---------------
    {
        const float* whp = g_whi + (size_t)oc0 * 1024;
        const float* wlp = g_wlo + (size_t)oc0 * 1024;
#pragma unroll
        for (int it = 0; it < 8; it++) {
            int idx = tid + it * 128, r = idx >> 3, ql = idx & 7, rr = r & 63;
            const float* src = ((r < 64) ? whp : wlp) + (size_t)rr * 1024 + ql * 4;
            uint32_t dst = sb + ((r < 64) ? 0u : (uint32_t)O_ALO) + swz((uint32_t)(rr * 128 + ql * 16));
            CP_ASYNC16(dst, src);
        }
        CP_COMMIT();
        {
            int ti = t0 - pad + jj;
            bpre0 = ((unsigned)ti < (unsigned)Lin) ? *(const float4*)&xb[(size_t)ti * ND + hh * 4]
                                                   : make_float4(0.f, 0.f, 0.f, 0.f);
            if (tid < 6) {
                int t2 = t0 - pad + jx;
                bpre1 = ((unsigned)t2 < (unsigned)Lin) ? *(const float4*)&xb[(size_t)t2 * ND + hh * 4]
                                                       : make_float4(0.f, 0.f, 0.f, 0.f);
            }
            spre = *(const float4*)&g_scale[hh * 4];
            hpre = *(const float4*)&g_shift[hh * 4];
        }
    }

    for (int cc = 0; cc < 32; cc++) {
        const uint32_t su = sb + (cc & 1) * STAGE;
        char* st = smem + (cc & 1) * STAGE;

        // ---- STS B first (regs -> stage cc; prior readers fenced by barrier cc-1)
        {
            int ti = t0 - pad + jj;
            bool ok = (unsigned)ti < (unsigned)Lin;
            float4 hi4, lo4;
#pragma unroll
            for (int q = 0; q < 4; q++) {
                float v = ok ? fmaxf(fmaf((&bpre0.x)[q], (&spre.x)[q], (&hpre.x)[q]), 0.f) : 0.f;
                float h = tf32r(v);
                (&hi4.x)[q] = h; (&lo4.x)[q] = tf32r(v - h);
            }
            uint32_t byte = (uint32_t)(jj * 32 + hh * 16) ^ ((uint32_t)(jj & 4) << 2);
            *(float4*)(st + O_BHI + byte) = hi4;
            *(float4*)(st + O_BLO + byte) = lo4;
            if (tid < 6) {
                int t2 = t0 - pad + jx;
                bool ok2 = (unsigned)t2 < (unsigned)Lin;
                float4 hi2, lo2;
#pragma unroll
                for (int q = 0; q < 4; q++) {
                    float v = ok2 ? fmaxf(fmaf((&bpre1.x)[q], (&spre.x)[q], (&hpre.x)[q]), 0.f) : 0.f;
                    float h = tf32r(v);
                    (&hi2.x)[q] = h; (&lo2.x)[q] = tf32r(v - h);
                }
                uint32_t byte2 = (uint32_t)(jx * 32 + hh * 16) ^ ((uint32_t)(jx & 4) << 2);
                *(float4*)(st + O_BHI + byte2) = hi2;
                *(float4*)(st + O_BLO + byte2) = lo2;
            }
        }
        CP_WAIT0();
        __syncthreads();      // single barrier per chunk

        // ---- prefetch chunk cc+1 (A via cp.async, B via regs) ------------------
        if (cc + 1 < 32) {
            const float* whp = g_whi + (size_t)oc0 * 1024 + (cc + 1) * 32;
            const float* wlp = g_wlo + (size_t)oc0 * 1024 + (cc + 1) * 32;
            uint32_t sd = sb + ((cc + 1) & 1) * STAGE;
#pragma unroll
            for (int it = 0; it < 8; it++) {
                int idx = tid + it * 128, r = idx >> 3, ql = idx & 7, rr = r & 63;
                const float* src = ((r < 64) ? whp : wlp) + (size_t)rr * 1024 + ql * 4;
                uint32_t dst = sd + ((r < 64) ? 0u : (uint32_t)O_ALO) + swz((uint32_t)(rr * 128 + ql * 16));
                CP_ASYNC16(dst, src);
            }
            CP_COMMIT();
            {
                const int ch0 = (cc + 1) * 8;
                int ti = t0 - pad + jj;
                bpre0 = ((unsigned)ti < (unsigned)Lin) ? *(const float4*)&xb[(size_t)ti * ND + ch0 + hh * 4]
                                                       : make_float4(0.f, 0.f, 0.f, 0.f);
                if (tid < 6) {
                    int t2 = t0 - pad + jx;
                    bpre1 = ((unsigned)t2 < (unsigned)Lin) ? *(const float4*)&xb[(size_t)t2 * ND + ch0 + hh * 4]
                                                           : make_float4(0.f, 0.f, 0.f, 0.f);
                }
                spre = *(const float4*)&g_scale[ch0 + hh * 4];
                hpre = *(const float4*)&g_shift[ch0 + hh * 4];
            }
        }

        // ---- mma on chunk cc: paired-x4 B loads, deferred A_lo -----------------
#pragma unroll
        for (int ks = 0; ks < 4; ks++) {
            uint32_t bh[4][2], bl[4][2], ah[2][4], al[2][4];
#pragma unroll
            for (int p = 0; p < 2; p++) {
                int r = brow0 + p * 16 + ks;
                uint32_t byte = ((uint32_t)(r * 32) + bcol) ^ ((uint32_t)(r & 4) << 2);
                uint32_t ad = su + O_BHI + byte;
                ldm_x4(bh[2 * p][0], bh[2 * p][1], bh[2 * p + 1][0], bh[2 * p + 1][1], ad);
                ldm_x4(bl[2 * p][0], bl[2 * p][1], bl[2 * p + 1][0], bl[2 * p + 1][1],
                       ad + (O_BLO - O_BHI));
            }
#pragma unroll
            for (int mt = 0; mt < 2; mt++) {
                uint32_t ad = su + (abase[mt] ^ (uint32_t)(ks << 5));
                ldm_x4(ah[mt][0], ah[mt][1], ah[mt][2], ah[mt][3], ad);
            }
#pragma unroll
            for (int mt = 0; mt < 2; mt++)
#pragma unroll
                for (int nt = 0; nt < 4; nt++) mma8(C[mt][nt], ah[mt], bh[nt]);
#pragma unroll
            for (int mt = 0; mt < 2; mt++)
#pragma unroll
                for (int nt = 0; nt < 4; nt++) mma8(C[mt][nt], ah[mt], bl[nt]);
#pragma unroll
            for (int mt = 0; mt < 2; mt++) {
                uint32_t ad = su + (abase[mt] ^ (uint32_t)(ks << 5)) + O_ALO;
                ldm_x4(al[mt][0], al[mt][1], al[mt][2], al[mt][3], ad);
            }
#pragma unroll
            for (int mt = 0; mt < 2; mt++)
#pragma unroll
                for (int nt = 0; nt < 4; nt++) mma8(C[mt][nt], al[mt], bh[nt]);
        }
    }
    __syncthreads();

    // ---- epilogue: bias + BN stats + smem transpose + coalesced store ----------
    double* ssumS = (double*)(smem + O_STAT);
    double* ssqS  = (double*)(smem + O_STAT + 512);
    if (tid < 64) { ssumS[tid] = 0.0; ssqS[tid] = 0.0; }
    float* eb = (float*)smem;                 // [64 tok][68 oc]
    __syncthreads();

#pragma unroll
    for (int mt = 0; mt < 2; mt++) {
#pragma unroll
        for (int h = 0; h < 2; h++) {
            int ocl = ocw + mt * 16 + (lane >> 2) + h * 8;
            float bv = bias[oc0 + ocl];
            double s = 0.0, q = 0.0;
#pragma unroll
            for (int nt = 0; nt < 4; nt++) {
#pragma unroll
                for (int p = 0; p < 2; p++) {
                    int n = tokw + nt * 8 + (lane & 3) * 2 + p;
                    float v = C[mt][nt][h * 2 + p] + bv;
                    eb[n * 68 + ocl] = v;
                    if (do_stats && (t0 + n < Lout)) { double d = (double)v; s += d; q += d * d; }
                }
            }
            if (do_stats) { atomicAdd(&ssumS[ocl], s); atomicAdd(&ssqS[ocl], q); }
        }
    }
    __syncthreads();

    for (int idx = tid; idx < 1024; idx += 128) {
        int r = idx >> 4, ql = idx & 15;
        if (t0 + r < Lout) {
            float4 v = *(float4*)&eb[r * 68 + ql * 4];
            size_t go = ((size_t)b * tstride + t0 + r) * ND + oc0 + ql * 4;
            *(float4*)&out[go] = v;
            if (split_ze) {
                float4 hi, lo;
                hi.x = tf32r(v.x); lo.x = tf32r(v.x - hi.x);
                hi.y = tf32r(v.y); lo.y = tf32r(v.y - hi.y);
                hi.z = tf32r(v.z); lo.z = tf32r(v.z - hi.z);
                hi.w = tf32r(v.w); lo.w = tf32r(v.w - hi.w);
                size_t zo = ((size_t)b * NT + t0 + r) * ND + oc0 + ql * 4;
                *(float4*)&g_zhi[zo] = hi;
                *(float4*)&g_zlo[zo] = lo;
            }
        }
    }
    if (do_stats && tid < 64) {
        atomicAdd(&g_sum[oc0 + tid], ssumS[tid]);
        atomicAdd(&g_sumsq[oc0 + tid], ssqS[tid]);
    }
}

// ---------------- layer 1: conv 12 -> 256, k=4, pad=2 (scalar; tiny K) ----------
__global__ __launch_bounds__(256) void conv1_kernel(
    const float* __restrict__ x, const float* __restrict__ w,
    const float* __restrict__ bias, float* __restrict__ out)
{
    __shared__ float in_s[12][68];
    __shared__ float w_s[64][49];
    __shared__ float o_s[64][65];
    __shared__ double ssum[64], ssq[64];

    const int tid = threadIdx.x;
    const int b = blockIdx.z, oc0 = blockIdx.y * 64, t0 = blockIdx.x * 64;
    const int ocl = tid & 63, tg = tid >> 6, tbase = tg * 16;
    const int Lout = 4097;

    for (int idx = tid; idx < 12 * 67; idx += 256) {
        int j = idx / 12, c = idx - j * 12;
        int ip = t0 - 2 + j;
        in_s[c][j] = ((unsigned)ip < 4096u) ? x[((size_t)b * NT + ip) * 12 + c] : 0.f;
    }
    for (int idx = tid; idx < 64 * 48; idx += 256) {
        int oc = idx / 48, r = idx - oc * 48;
        w_s[oc][r] = w[(size_t)(oc0 + oc) * 48 + r];
    }
    __syncthreads();

    float acc[16];
#pragma unroll
    for (int u = 0; u < 16; u++) acc[u] = 0.f;
#pragma unroll
    for (int c = 0; c < 12; c++) {
        float v[19];
#pragma unroll
        for (int u = 0; u < 19; u++) v[u] = in_s[c][tbase + u];
        float w0 = w_s[ocl][c * 4 + 0], w1 = w_s[ocl][c * 4 + 1];
        float w2 = w_s[ocl][c * 4 + 2], w3 = w_s[ocl][c * 4 + 3];
#pragma unroll
        for (int u = 0; u < 16; u++)
            acc[u] = fmaf(w3, v[u + 3], fmaf(w2, v[u + 2], fmaf(w1, v[u + 1], fmaf(w0, v[u], acc[u]))));
    }
    const float bv = bias[oc0 + ocl];
#pragma unroll
    for (int u = 0; u < 16; u++) acc[u] += bv;

    {
        double s = 0.0, q = 0.0;
#pragma unroll
        for (int u = 0; u < 16; u++)
            if (t0 + tbase + u < Lout) { double a = (double)acc[u]; s += a; q += a * a; }
        __syncthreads();
        if (tid < 64) { ssum[tid] = 0.0; ssq[tid] = 0.0; }
        __syncthreads();
        atomicAdd(&ssum[ocl], s);
        atomicAdd(&ssq[ocl], q);
        __syncthreads();
        if (tid < 64) {
            atomicAdd(&g_sum[oc0 + tid], ssum[tid]);
            atomicAdd(&g_sumsq[oc0 + tid], ssq[tid]);
        }
    }

    __syncthreads();
#pragma unroll
    for (int u = 0; u < 16; u++) o_s[ocl][tbase + u] = acc[u];
    __syncthreads();
    float* ob = out + ((size_t)b * TS_INT + t0) * ND + oc0;
    for (int idx = tid; idx < 4096; idx += 256) {
        int t = idx >> 6, oc = idx & 63;
        if (t0 + t < Lout) ob[(size_t)t * ND + oc] = o_s[oc][t];
    }
}

// ---------------- BN stats -> scale/shift for next layer; resets stats ----------
__global__ void scaleshift_kernel(const float* __restrict__ g, const float* __restrict__ be, double N)
{
    int c = threadIdx.x;
    double m = g_sum[c] / N;
    double var = g_sumsq[c] / N - m * m;
    double r = 1.0 / sqrt(var + 1e-5);
    double sc = (double)g[c] * r;
    g_scale[c] = (float)sc;
    g_shift[c] = (float)((double)be[c] - m * sc);
    g_sum[c] = 0.0;
    g_sumsq[c] = 0.0;
}

// ---------------- ||codebook_k||^2 (exact fp32) ---------------------------------
__global__ void cnorm_kernel(const float* __restrict__ cb)
{
    int gw = (blockIdx.x * 256 + threadIdx.x) >> 5;
    int lane = threadIdx.x & 31;
    float s = 0.f;
    const float* row = cb + (size_t)gw * ND;
    for (int d = lane; d < ND; d += 32) { float v = row[d]; s = fmaf(v, v, s); }
#pragma unroll
    for (int off = 16; off; off >>= 1) s += __shfl_xor_sync(0xffffffffu, s, off);
    if (lane == 0) g_cnorm[gw] = s;
}

// ============ VQ argmin as mma.sync tf32 3x-split GEMM (src=g_zhi/lo) ===========
__global__ __launch_bounds__(256, 1) void vqmma_kernel(int* __restrict__ ids)
{
    extern __shared__ __align__(1024) char smem[];
    const int tid = threadIdx.x;
    const int wid = tid >> 5, lane = tid & 31;
    const int tok0 = blockIdx.x * 64;
    const int tokw = (wid >> 2) * 32;
    const int cw = (wid & 3) * 16;

    const uint32_t sb = smem_u32(smem);

    {
        const float* zhi = g_zhi;
        const float* zlo = g_zlo;
#pragma unroll
        for (int it = 0; it < 32; it++) {
            int idx = tid + it * 256;
            int q = idx & 7, r = (idx >> 3) & 63, kc = (idx >> 9) & 7, half = idx >> 12;
            const float* src = (half ? zlo : zhi) + ((size_t)(tok0 + r) * 256 + kc * 32 + q * 4);
            uint32_t dst = sb + half * VQ_ZLO + kc * 8192 + swz((uint32_t)(r * 128 + q * 16));
            CP_ASYNC16(dst, src);
        }
        CP_COMMIT();
    }
    {
#pragma unroll
        for (int it = 0; it < 4; it++) {
            int idx = tid + it * 256;
            int q = idx & 7, r = (idx >> 3) & 63, half = idx >> 9;
            const float* src = (half ? g_wlo : g_whi) + ((size_t)r * 256 + q * 4);
            uint32_t dst = sb + VQ_B + half * 8192 + swz((uint32_t)(r * 128 + q * 16));
            CP_ASYNC16(dst, src);
        }
        CP_COMMIT();
    }

    uint32_t abase[2];
    {
        int ar = tokw + (lane & 7) + ((lane >> 3) & 1) * 8;
        int aq = (lane >> 4) & 1;
#pragma unroll
        for (int mt = 0; mt < 2; mt++) {
            int r = ar + mt * 16;
            abase[mt] = (uint32_t)(r * 128 + ((aq * 16) ^ ((r & 7) << 4)));
        }
    }
    const int brow = cw + (lane & 7) + (((lane >> 4) & 1) << 3);
    const uint32_t bcol = (uint32_t)(((lane >> 3) & 1) << 4);

    unsigned long long best[4];
#pragma unroll
    for (int i = 0; i < 4; i++) best[i] = ~0ull;

    float C[2][2][4];

    for (int s = 0; s < 128; s++) {
        const int ct = s >> 3, kc = s & 7;
        const uint32_t bst = sb + VQ_B + (s & 1) * VQ_BST;

        CP_WAIT0();
        __syncthreads();

        if (s + 1 < 128) {
            const int nct = (s + 1) >> 3, nkc = (s + 1) & 7;
            uint32_t sd = sb + VQ_B + ((s + 1) & 1) * VQ_BST;
#pragma unroll
            for (int it = 0; it < 4; it++) {
                int idx = tid + it * 256;
                int q = idx & 7, r = (idx >> 3) & 63, half = idx >> 9;
                const float* src = (half ? g_wlo : g_whi) + ((size_t)(nct * 64 + r) * 256 + nkc * 32 + q * 4);
                uint32_t dst = sd + half * 8192 + swz((uint32_t)(r * 128 + q * 16));
                CP_ASYNC16(dst, src);
            }
            CP_COMMIT();
        }

        if (kc == 0) {
#pragma unroll
            for (int mt = 0; mt < 2; mt++)
#pragma unroll
                for (int nt = 0; nt < 2; nt++)
#pragma unroll
                    for (int q = 0; q < 4; q++) C[mt][nt][q] = 0.f;
        }

        const uint32_t za = sb + kc * 8192;
#pragma unroll
        for (int ks = 0; ks < 4; ks++) {
            uint32_t bh[2][2], bl[2][2], ah[2][4], al[2][4];
            {
                uint32_t byte = (uint32_t)(brow * 128) + (((uint32_t)(ks * 32) + bcol) ^ ((uint32_t)(brow & 7) << 4));
                uint32_t ad = bst + byte;
                ldm_x4(bh[0][0], bh[0][1], bh[1][0], bh[1][1], ad);
                ldm_x4(bl[0][0], bl[0][1], bl[1][0], bl[1][1], ad + 8192);
            }
#pragma unroll
            for (int mt = 0; mt < 2; mt++) {
                uint32_t ad = za + (abase[mt] ^ (uint32_t)(ks << 5));
                ldm_x4(ah[mt][0], ah[mt][1], ah[mt][2], ah[mt][3], ad);
            }
#pragma unroll
            for (int mt = 0; mt < 2; mt++)
#pragma unroll
                for (int nt = 0; nt < 2; nt++) mma8(C[mt][nt], ah[mt], bh[nt]);
#pragma unroll
            for (int mt = 0; mt < 2; mt++)
#pragma unroll
                for (int nt = 0; nt < 2; nt++) mma8(C[mt][nt], ah[mt], bl[nt]);
#pragma unroll
            for (int mt = 0; mt < 2; mt++) {
                uint32_t ad = za + VQ_ZLO + (abase[mt] ^ (uint32_t)(ks << 5));
                ldm_x4(al[mt][0], al[mt][1], al[mt][2], al[mt][3], ad);
            }
#pragma unroll
            for (int mt = 0; mt < 2; mt++)
#pragma unroll
                for (int nt = 0; nt < 2; nt++) mma8(C[mt][nt], al[mt], bh[nt]);
        }

        if (kc == 7) {
#pragma unroll
            for (int mt = 0; mt < 2; mt++)
#pragma unroll
                for (int h = 0; h < 2; h++) {
#pragma unroll
                    for (int nt = 0; nt < 2; nt++)
#pragma unroll
                        for (int p = 0; p < 2; p++) {
                            int code = ct * 64 + cw + nt * 8 + (lane & 3) * 2 + p;
                            float dist = fmaf(-2.f, C[mt][nt][h * 2 + p], g_cnorm[code]);
                            unsigned long long cand =
                                ((unsigned long long)fbits_ord(dist) << 32) | (unsigned)code;
                            unsigned long long* bp = &best[mt * 2 + h];
                            if (cand < *bp) *bp = cand;
                        }
                }
        }
    }

#pragma unroll
    for (int off = 1; off <= 2; off <<= 1) {
#pragma unroll
        for (int i = 0; i < 4; i++) {
            unsigned long long o = __shfl_xor_sync(0xffffffffu, best[i], off);
            if (o < best[i]) best[i] = o;
        }
    }
    unsigned long long* red = (unsigned long long*)(smem + VQ_RED);   // [64][4]
    __syncthreads();
    if ((lane & 3) == 0) {
#pragma unroll
        for (int mt = 0; mt < 2; mt++)
#pragma unroll
            for (int h = 0; h < 2; h++) {
                int trow = tokw + mt * 16 + h * 8 + (lane >> 2);
                red[trow * 4 + (wid & 3)] = best[mt * 2 + h];
            }
    }
    __syncthreads();
    if (tid < 64) {
        unsigned long long m = red[tid * 4];
#pragma unroll
        for (int i = 1; i < 4; i++) { unsigned long long o = red[tid * 4 + i]; if (o < m) m = o; }
        ids[tok0 + tid] = (int)(m & 0xFFFFFFFFu);
    }
}

// ---------------- VQ tail: counts + z_q + segment sums --------------------------
__global__ __launch_bounds__(256) void vqtail_kernel(
    const float* __restrict__ ze, const float* __restrict__ cb, float* __restrict__ zq)
{
    __shared__ int sid[64];
    const int tid = threadIdx.x;
    const int tok0 = blockIdx.x * 64;
    if (tid < 64) sid[tid] = g_ids[tok0 + tid];
    __syncthreads();
    if (tid < 64) atomicAdd(&g_cnt[sid[tid]], 1.0f);
    for (int e = tid; e < 64 * ND; e += 256) {
        int r = e >> 8, d = e & 255;
        int code = sid[r];
        size_t gz = (size_t)(tok0 + r) * ND + d;
        float zev = ze[gz];
        float cbv = cb[(size_t)code * ND + d];
        zq[gz] = zev + (cbv - zev);
        atomicAdd(&g_sumcur[(size_t)code * ND + d], zev);
    }
}

// ---------------- EMA epilogue ---------------------------------------------------
__global__ void ema1_kernel(const float* __restrict__ ecs, float* __restrict__ necs)
{
    __shared__ float red[1024];
    int k = threadIdx.x;
    float ne = ecs[k] * 0.99f + 0.01f * g_cnt[k];
    necs[k] = ne;
    g_cnt[k] = 0.f;
    red[k] = ne;
    __syncthreads();
    for (int off = 512; off; off >>= 1) {
        if (k < off) red[k] += red[k + off];
        __syncthreads();
    }
    if (k == 0) g_n = red[0];
}

__global__ void ema2_kernel(const float* __restrict__ ema_w, const float* __restrict__ necs,
                            float* __restrict__ ncb)
{
    int k = blockIdx.x, d = threadIdx.x;
    float n = g_n;
    float smoothed = (necs[k] + 1e-5f) / (n + 1024.f * 1e-5f) * n;
    size_t idx = (size_t)k * ND + d;
    float nw = ema_w[idx] * 0.99f + 0.01f * g_sumcur[idx];
    ncb[idx] = nw / smoothed;
    g_sumcur[idx] = 0.f;
}

// ---------------- host launcher ---------------------------------------------------
extern "C" void kernel_launch(void* const* d_in, const int* in_sizes, int n_in,
                              void* d_out, int out_size)
{
    const float* X = (const float*)d_in[0];
    const float *W[6], *Bi[6], *G[5], *Be[5];

    bool sig = (in_sizes[3] == 256);
    if (!sig) {
        for (int i = 0; i < 6; i++) { W[i] = (const float*)d_in[1 + 2 * i]; Bi[i] = (const float*)d_in[2 + 2 * i]; }
        for (int i = 0; i < 5; i++) { G[i] = (const float*)d_in[13 + 2 * i]; Be[i] = (const float*)d_in[14 + 2 * i]; }
    } else {
        for (int i = 0; i < 5; i++) {
            W[i]  = (const float*)d_in[1 + 4 * i];
            Bi[i] = (const float*)d_in[2 + 4 * i];
            G[i]  = (const float*)d_in[3 + 4 * i];
            Be[i] = (const float*)d_in[4 + 4 * i];
        }
        W[5] = (const float*)d_in[21];
        Bi[5] = (const float*)d_in[22];
    }
    const float* codebook = (const float*)d_in[23];
    const float* ema_w    = (const float*)d_in[24];
    const float* ecs      = (const float*)d_in[25];

    float* out  = (float*)d_out;
    float* ze   = out;
    float* zq   = out + (size_t)33554432;
    float* ncb  = out + (size_t)67108864;
    float* necs = out + (size_t)67371008;

    float *bufA = nullptr, *bufB = nullptr;
    cudaGetSymbolAddress((void**)&bufA, g_bufA);
    cudaGetSymbolAddress((void**)&bufB, g_bufB);
    int* idsp = nullptr;
    cudaGetSymbolAddress((void**)&idsp, g_ids);

    cudaFuncSetAttribute(convmma_kernel, cudaFuncAttributeMaxDynamicSharedMemorySize, SMEM_MMA);
    cudaFuncSetAttribute(vqmma_kernel, cudaFuncAttributeMaxDynamicSharedMemorySize, SMEM_VQ);

    dim3 blk(256);
    dim3 cblk(128);
    conv1_kernel<<<dim3(65, 4, 32), blk>>>(X, W[0], Bi[0], bufA);
    scaleshift_kernel<<<1, 256>>>(G[0], Be[0], (double)(32.0 * 4097.0));
    wsplit_kernel<<<256, 256>>>(W[1]);
    convmma_kernel<<<dim3(64, 4, 32), cblk, SMEM_MMA>>>(bufA, Bi[1], bufB, 4097, 4096, 1, TS_INT, 1, 0);
    scaleshift_kernel<<<1, 256>>>(G[1], Be[1], (double)(32.0 * 4096.0));
    wsplit_kernel<<<256, 256>>>(W[2]);
    convmma_kernel<<<dim3(65, 4, 32), cblk, SMEM_MMA>>>(bufB, Bi[2], bufA, 4096, 4097, 2, TS_INT, 1, 0);
    scaleshift_kernel<<<1, 256>>>(G[2], Be[2], (double)(32.0 * 4097.0));
    wsplit_kernel<<<256, 256>>>(W[3]);
    convmma_kernel<<<dim3(64, 4, 32), cblk, SMEM_MMA>>>(bufA, Bi[3], bufB, 4097, 4096, 1, TS_INT, 1, 0);
    scaleshift_kernel<<<1, 256>>>(G[3], Be[3], (double)(32.0 * 4096.0));
    wsplit_kernel<<<256, 256>>>(W[4]);
    convmma_kernel<<<dim3(65, 4, 32), cblk, SMEM_MMA>>>(bufB, Bi[4], bufA, 4096, 4097, 2, TS_INT, 1, 0);
    scaleshift_kernel<<<1, 256>>>(G[4], Be[4], (double)(32.0 * 4097.0));
    wsplit_kernel<<<256, 256>>>(W[5]);
    // L6: writes z_e AND its tf32 hi/lo split (fused)
    convmma_kernel<<<dim3(64, 4, 32), cblk, SMEM_MMA>>>(bufA, Bi[5], ze, 4097, 4096, 1, 4096, 0, 1);

    csplit_kernel<<<256, 256>>>(codebook);
    cnorm_kernel<<<128, 256>>>(codebook);
    vqmma_kernel<<<2048, 256, SMEM_VQ>>>(idsp);
    vqtail_kernel<<<2048, 256>>>(ze, codebook, zq);
    ema1_kernel<<<1, 1024>>>(ecs, necs);
    ema2_kernel<<<1024, 256>>>(ema_w, necs, ncb);
}

// round 16
// speedup vs baseline: 1.1161x; 1.0057x over previous
#include <cuda_runtime.h>
#include <cstdint>

#define NB 32
#define NT 4096
#define ND 256
#define NK 1024
#define TS_INT 4104        // token stride of intermediate activation buffers

// ---------------- scratch (static device globals; no allocation) ----------------
__device__ float  g_bufA[(size_t)NB * TS_INT * ND];
__device__ float  g_bufB[(size_t)NB * TS_INT * ND];
__device__ float  g_zhi[(size_t)NB * NT * ND];   // z_e tf32 hi (written by L6 epilogue)
__device__ float  g_zlo[(size_t)NB * NT * ND];   // z_e tf32 lo
__device__ float  g_wsp[(size_t)5 * 2 * ND * 1024];  // all conv weight splits [layer][hi/lo]
__device__ float  g_whi[(size_t)ND * 1024];      // vq codebook tf32 hi
__device__ float  g_wlo[(size_t)ND * 1024];
__device__ double g_sum[ND];
__device__ double g_sumsq[ND];
__device__ float  g_scale[ND];
__device__ float  g_shift[ND];
__device__ float  g_cnorm[NK];
__device__ float  g_cnt[NK];
__device__ float  g_sumcur[(size_t)NK * ND];
__device__ float  g_n;
__device__ int    g_ids[(size_t)NB * NT];

// ---------------- helpers --------------------------------------------------------
__device__ __forceinline__ uint32_t smem_u32(const void* p) {
    uint32_t a;
    asm("{ .reg .u64 t; cvta.to.shared.u64 t, %1; cvt.u32.u64 %0, t; }" : "=r"(a) : "l"(p));
    return a;
}
__device__ __forceinline__ float tf32r(float x) {
    float r;
    asm("cvt.rna.tf32.f32 %0, %1;" : "=f"(r) : "f"(x));
    return r;
}
__device__ __forceinline__ uint32_t swz(uint32_t off) { return off ^ ((off >> 3) & 0x70); }

__device__ __forceinline__ void ldm_x4(uint32_t& r0, uint32_t& r1, uint32_t& r2, uint32_t& r3, uint32_t a) {
    asm volatile("ldmatrix.sync.aligned.m8n8.x4.shared.b16 {%0,%1,%2,%3}, [%4];"
                 : "=r"(r0), "=r"(r1), "=r"(r2), "=r"(r3) : "r"(a));
}
__device__ __forceinline__ void mma8(float* c, const uint32_t* a, const uint32_t* b) {
    asm volatile("mma.sync.aligned.m16n8k8.row.col.f32.tf32.tf32.f32 "
        "{%0,%1,%2,%3}, {%4,%5,%6,%7}, {%8,%9}, {%0,%1,%2,%3};"
        : "+f"(c[0]), "+f"(c[1]), "+f"(c[2]), "+f"(c[3])
        : "r"(a[0]), "r"(a[1]), "r"(a[2]), "r"(a[3]), "r"(b[0]), "r"(b[1]));
}
#define CP_ASYNC16(dst, src) asm volatile("cp.async.cg.shared.global [%0], [%1], 16;" :: "r"(dst), "l"(src))
#define CP_COMMIT()  asm volatile("cp.async.commit_group;" ::: "memory")
#define CP_WAIT0()   asm volatile("cp.async.wait_group 0;" ::: "memory")

// order-preserving float -> u32 map (finite inputs)
__device__ __forceinline__ uint32_t fbits_ord(float f) {
    uint32_t u = __float_as_uint(f);
    return (u & 0x80000000u) ? ~u : (u | 0x80000000u);
}

// conv smem stage (64oc x 64tok tile): A_hi[64 x 128B] | A_lo | B_hi[67+ x 32B] | B_lo
#define O_ALO 8192
#define O_BHI 16384
#define O_BLO (16384 + 2304)
#define STAGE 21504
#define O_STAT (2 * STAGE)
#define SMEM_MMA (O_STAT + 2048)

// vq smem: z-cache hi (64KB) | z lo (64KB) | 2 B stages | red
#define VQ_ZLO 65536
#define VQ_B   131072
#define VQ_BST 16384
#define VQ_RED (131072 + 2 * VQ_BST)
#define SMEM_VQ (VQ_RED + 2048)

// ---------------- one-shot weight split for ALL 5 D->D layers -------------------
// in: w[oc][ch][kk]  ->  g_wsp[layer][hi/lo][oc][ch>>3][kk][ch&7], tf32 split
__global__ void wsplit_all_kernel(const float* __restrict__ w0, const float* __restrict__ w1,
                                  const float* __restrict__ w2, const float* __restrict__ w3,
                                  const float* __restrict__ w4)
{
    const float* wp = (blockIdx.y == 0) ? w0 : (blockIdx.y == 1) ? w1
                    : (blockIdx.y == 2) ? w2 : (blockIdx.y == 3) ? w3 : w4;
    int i = blockIdx.x * 256 + threadIdx.x;      // 65536 = (oc, ch)
    int oc = i >> 8, ch = i & 255;
    float4 v = *(const float4*)&wp[(size_t)oc * 1024 + ch * 4];
    float* whi = g_wsp + (size_t)blockIdx.y * 2 * ND * 1024;
    float* wlo = whi + (size_t)ND * 1024;
    size_t base = (size_t)oc * 1024 + (ch >> 3) * 32 + (ch & 7);
#pragma unroll
    for (int kk = 0; kk < 4; kk++) {
        float x = (&v.x)[kk];
        float hi = tf32r(x);
        whi[base + kk * 8] = hi;
        wlo[base + kk * 8] = tf32r(x - hi);
    }
}

// ---------------- codebook tf32 hi/lo split (row-major; for VQ) -----------------
__global__ void csplit_kernel(const float* __restrict__ cb)
{
    size_t i = (size_t)blockIdx.x * 256 + threadIdx.x;   // float4 index, 65536 total
    float4 v = ((const float4*)cb)[i];
    float4 hi, lo;
    hi.x = tf32r(v.x); lo.x = tf32r(v.x - hi.x);
    hi.y = tf32r(v.y); lo.y = tf32r(v.y - hi.y);
    hi.z = tf32r(v.z); lo.z = tf32r(v.z - hi.z);
    hi.w = tf32r(v.w); lo.w = tf32r(v.w - hi.w);
    ((float4*)g_whi)[i] = hi;
    ((float4*)g_wlo)[i] = lo;
}

// ============ conv D->D: mma.sync tf32 3x-split, 4 CTAs/SM (round-14) ===========
// CTA: 128 threads (4 warps), tile 64 oc x 64 tok, warp tile 32x32 (mt=2, nt=4).
// K = 32 chunks of (8 ch x 4 taps). split_ze: L6 also writes tf32 hi/lo of out.
__global__ __launch_bounds__(128, 4) void convmma_kernel(
    const float* __restrict__ in, const float* __restrict__ wsp,
    const float* __restrict__ bias,
    float* __restrict__ out, int Lin, int Lout, int pad, int tstride,
    int do_stats, int split_ze)
{
    extern __shared__ __align__(1024) char smem[];
    const int tid = threadIdx.x;
    const int wid = tid >> 5, lane = tid & 31;
    const int b = blockIdx.z, oc0 = blockIdx.y * 64, t0 = blockIdx.x * 64;
    const int ocw = (wid & 1) * 32;
    const int tokw = (wid >> 1) * 32;

    const uint32_t sb = smem_u32(smem);
    const float* xb = in + (size_t)b * TS_INT * ND;
    const float* wbh = wsp + (size_t)oc0 * 1024;
    const float* wbl = wsp + (size_t)ND * 1024 + (size_t)oc0 * 1024;

    uint32_t abase[2];
    {
        int ar = ocw + (lane & 7) + ((lane >> 3) & 1) * 8;
        int aq = (lane >> 4) & 1;
#pragma unroll
        for (int mt = 0; mt < 2; mt++) {
            int r = ar + mt * 16;
            abase[mt] = (uint32_t)(r * 128 + ((aq * 16) ^ ((r & 7) << 4)));
        }
    }
    const int brow0 = tokw + (lane & 7) + (((lane >> 4) & 1) << 3);
    const uint32_t bcol = (uint32_t)(((lane >> 3) & 1) << 4);

    float C[2][4][4];
#pragma unroll
    for (int mt = 0; mt < 2; mt++)
#pragma unroll
        for (int nt = 0; nt < 4; nt++)
#pragma unroll
            for (int q = 0; q < 4; q++) C[mt][nt][q] = 0.f;

    const int jj = tid >> 1, hh = tid & 1;
    const int jx = 64 + (tid >> 1);
    float4 bpre0, bpre1, spre, hpre;

    // ---- prologue: stage 0 ------------------------------------------------------
    {
#pragma unroll
        for (int it = 0; it < 8; it++) {
            int idx = tid + it * 128, r = idx >> 3, ql = idx & 7, rr = r & 63;
            const float* src = ((r < 64) ? wbh : wbl) + (size_t)rr * 1024 + ql * 4;
            uint32_t dst = sb + ((r < 64) ? 0u : (uint32_t)O_ALO) + swz((uint32_t)(rr * 128 + ql * 16));
            CP_ASYNC16(dst, src);
        }
        CP_COMMIT();
        {
            int ti = t0 - pad + jj;
            bpre0 = ((unsigned)ti < (unsigned)Lin) ? *(const float4*)&xb[(size_t)ti * ND + hh * 4]
                                                   : make_float4(0.f, 0.f, 0.f, 0.f);
            if (tid < 6) {
                int t2 = t0 - pad + jx;
                bpre1 = ((unsigned)t2 < (unsigned)Lin) ? *(const float4*)&xb[(size_t)t2 * ND + hh * 4]
                                                       : make_float4(0.f, 0.f, 0.f, 0.f);
            }
            spre = *(const float4*)&g_scale[hh * 4];
            hpre = *(const float4*)&g_shift[hh * 4];
        }
    }

    for (int cc = 0; cc < 32; cc++) {
        const uint32_t su = sb + (cc & 1) * STAGE;
        char* st = smem + (cc & 1) * STAGE;

        {
            int ti = t0 - pad + jj;
            bool ok = (unsigned)ti < (unsigned)Lin;
            float4 hi4, lo4;
#pragma unroll
            for (int q = 0; q < 4; q++) {
                float v = ok ? fmaxf(fmaf((&bpre0.x)[q], (&spre.x)[q], (&hpre.x)[q]), 0.f) : 0.f;
                float h = tf32r(v);
                (&hi4.x)[q] = h; (&lo4.x)[q] = tf32r(v - h);
            }
            uint32_t byte = (uint32_t)(jj * 32 + hh * 16) ^ ((uint32_t)(jj & 4) << 2);
            *(float4*)(st + O_BHI + byte) = hi4;
            *(float4*)(st + O_BLO + byte) = lo4;
            if (tid < 6) {
                int t2 = t0 - pad + jx;
                bool ok2 = (unsigned)t2 < (unsigned)Lin;
                float4 hi2, lo2;
#pragma unroll
                for (int q = 0; q < 4; q++) {
                    float v = ok2 ? fmaxf(fmaf((&bpre1.x)[q], (&spre.x)[q], (&hpre.x)[q]), 0.f) : 0.f;
                    float h = tf32r(v);
                    (&hi2.x)[q] = h; (&lo2.x)[q] = tf32r(v - h);
                }
                uint32_t byte2 = (uint32_t)(jx * 32 + hh * 16) ^ ((uint32_t)(jx & 4) << 2);
                *(float4*)(st + O_BHI + byte2) = hi2;
                *(float4*)(st + O_BLO + byte2) = lo2;
            }
        }
        CP_WAIT0();
        __syncthreads();      // single barrier per chunk

        if (cc + 1 < 32) {
            const float* whp = wbh + (cc + 1) * 32;
            const float* wlp = wbl + (cc + 1) * 32;
            uint32_t sd = sb + ((cc + 1) & 1) * STAGE;
#pragma unroll
            for (int it = 0; it < 8; it++) {
                int idx = tid + it * 128, r = idx >> 3, ql = idx & 7, rr = r & 63;
                const float* src = ((r < 64) ? whp : wlp) + (size_t)rr * 1024 + ql * 4;
                uint32_t dst = sd + ((r < 64) ? 0u : (uint32_t)O_ALO) + swz((uint32_t)(rr * 128 + ql * 16));
                CP_ASYNC16(dst, src);
            }
            CP_COMMIT();
            {
                const int ch0 = (cc + 1) * 8;
                int ti = t0 - pad + jj;
                bpre0 = ((unsigned)ti < (unsigned)Lin) ? *(const float4*)&xb[(size_t)ti * ND + ch0 + hh * 4]
                                                       : make_float4(0.f, 0.f, 0.f, 0.f);
                if (tid < 6) {
                    int t2 = t0 - pad + jx;
                    bpre1 = ((unsigned)t2 < (unsigned)Lin) ? *(const float4*)&xb[(size_t)t2 * ND + ch0 + hh * 4]
                                                           : make_float4(0.f, 0.f, 0.f, 0.f);
                }
                spre = *(const float4*)&g_scale[ch0 + hh * 4];
                hpre = *(const float4*)&g_shift[ch0 + hh * 4];
            }
        }

#pragma unroll
        for (int ks = 0; ks < 4; ks++) {
            uint32_t bh[4][2], bl[4][2], ah[2][4], al[2][4];
#pragma unroll
            for (int p = 0; p < 2; p++) {
                int r = brow0 + p * 16 + ks;
                uint32_t byte = ((uint32_t)(r * 32) + bcol) ^ ((uint32_t)(r & 4) << 2);
                uint32_t ad = su + O_BHI + byte;
                ldm_x4(bh[2 * p][0], bh[2 * p][1], bh[2 * p + 1][0], bh[2 * p + 1][1], ad);
                ldm_x4(bl[2 * p][0], bl[2 * p][1], bl[2 * p + 1][0], bl[2 * p + 1][1],
                       ad + (O_BLO - O_BHI));
            }
#pragma unroll
            for (int mt = 0; mt < 2; mt++) {
                uint32_t ad = su + (abase[mt] ^ (uint32_t)(ks << 5));
                ldm_x4(ah[mt][0], ah[mt][1], ah[mt][2], ah[mt][3], ad);
            }
#pragma unroll
            for (int mt = 0; mt < 2; mt++)
#pragma unroll
                for (int nt = 0; nt < 4; nt++) mma8(C[mt][nt], ah[mt], bh[nt]);
#pragma unroll
            for (int mt = 0; mt < 2; mt++)
#pragma unroll
                for (int nt = 0; nt < 4; nt++) mma8(C[mt][nt], ah[mt], bl[nt]);
#pragma unroll
            for (int mt = 0; mt < 2; mt++) {
                uint32_t ad = su + (abase[mt] ^ (uint32_t)(ks << 5)) + O_ALO;
                ldm_x4(al[mt][0], al[mt][1], al[mt][2], al[mt][3], ad);
            }
#pragma unroll
            for (int mt = 0; mt < 2; mt++)
#pragma unroll
                for (int nt = 0; nt < 4; nt++) mma8(C[mt][nt], al[mt], bh[nt]);
        }
    }
    __syncthreads();

    // ---- epilogue: bias + BN stats + smem transpose + coalesced store ----------
    double* ssumS = (double*)(smem + O_STAT);
    double* ssqS  = (double*)(smem + O_STAT + 512);
    if (tid < 64) { ssumS[tid] = 0.0; ssqS[tid] = 0.0; }
    float* eb = (float*)smem;                 // [64 tok][68 oc]
    __syncthreads();

#pragma unroll
    for (int mt = 0; mt < 2; mt++) {
#pragma unroll
        for (int h = 0; h < 2; h++) {
            int ocl = ocw + mt * 16 + (lane >> 2) + h * 8;
            float bv = bias[oc0 + ocl];
            double s = 0.0, q = 0.0;
#pragma unroll
            for (int nt = 0; nt < 4; nt++) {
#pragma unroll
                for (int p = 0; p < 2; p++) {
                    int n = tokw + nt * 8 + (lane & 3) * 2 + p;
                    float v = C[mt][nt][h * 2 + p] + bv;
                    eb[n * 68 + ocl] = v;
                    if (do_stats && (t0 + n < Lout)) { double d = (double)v; s += d; q += d * d; }
                }
            }
            if (do_stats) { atomicAdd(&ssumS[ocl], s); atomicAdd(&ssqS[ocl], q); }
        }
    }
    __syncthreads();

    for (int idx = tid; idx < 1024; idx += 128) {
        int r = idx >> 4, ql = idx & 15;
        if (t0 + r < Lout) {
            float4 v = *(float4*)&eb[r * 68 + ql * 4];
            size_t go = ((size_t)b * tstride + t0 + r) * ND + oc0 + ql * 4;
            *(float4*)&out[go] = v;
            if (split_ze) {
                float4 hi, lo;
                hi.x = tf32r(v.x); lo.x = tf32r(v.x - hi.x);
                hi.y = tf32r(v.y); lo.y = tf32r(v.y - hi.y);
                hi.z = tf32r(v.z); lo.z = tf32r(v.z - hi.z);
                hi.w = tf32r(v.w); lo.w = tf32r(v.w - hi.w);
                size_t zo = ((size_t)b * NT + t0 + r) * ND + oc0 + ql * 4;
                *(float4*)&g_zhi[zo] = hi;
                *(float4*)&g_zlo[zo] = lo;
            }
        }
    }
    if (do_stats && tid < 64) {
        atomicAdd(&g_sum[oc0 + tid], ssumS[tid]);
        atomicAdd(&g_sumsq[oc0 + tid], ssqS[tid]);
    }
}

// ---------------- layer 1: conv 12 -> 256, k=4, pad=2 (scalar; tiny K) ----------
__global__ __launch_bounds__(256) void conv1_kernel(
    const float* __restrict__ x, const float* __restrict__ w,
    const float* __restrict__ bias, float* __restrict__ out)
{
    __shared__ float in_s[12][68];
    __shared__ float w_s[64][49];
    __shared__ float o_s[64][65];
    __shared__ double ssum[64], ssq[64];

    const int tid = threadIdx.x;
    const int b = blockIdx.z, oc0 = blockIdx.y * 64, t0 = blockIdx.x * 64;
    const int ocl = tid & 63, tg = tid >> 6, tbase = tg * 16;
    const int Lout = 4097;

    for (int idx = tid; idx < 12 * 67; idx += 256) {
        int j = idx / 12, c = idx - j * 12;
        int ip = t0 - 2 + j;
        in_s[c][j] = ((unsigned)ip < 4096u) ? x[((size_t)b * NT + ip) * 12 + c] : 0.f;
    }
    for (int idx = tid; idx < 64 * 48; idx += 256) {
        int oc = idx / 48, r = idx - oc * 48;
        w_s[oc][r] = w[(size_t)(oc0 + oc) * 48 + r];
    }
    __syncthreads();

    float acc[16];
#pragma unroll
    for (int u = 0; u < 16; u++) acc[u] = 0.f;
#pragma unroll
    for (int c = 0; c < 12; c++) {
        float v[19];
#pragma unroll
        for (int u = 0; u < 19; u++) v[u] = in_s[c][tbase + u];
        float w0 = w_s[ocl][c * 4 + 0], w1 = w_s[ocl][c * 4 + 1];
        float w2 = w_s[ocl][c * 4 + 2], w3 = w_s[ocl][c * 4 + 3];
#pragma unroll
        for (int u = 0; u < 16; u++)
            acc[u] = fmaf(w3, v[u + 3], fmaf(w2, v[u + 2], fmaf(w1, v[u + 1], fmaf(w0, v[u], acc[u]))));
    }
    const float bv = bias[oc0 + ocl];
#pragma unroll
    for (int u = 0; u < 16; u++) acc[u] += bv;

    {
        double s = 0.0, q = 0.0;
#pragma unroll
        for (int u = 0; u < 16; u++)
            if (t0 + tbase + u < Lout) { double a = (double)acc[u]; s += a; q += a * a; }
        __syncthreads();
        if (tid < 64) { ssum[tid] = 0.0; ssq[tid] = 0.0; }
        __syncthreads();
        atomicAdd(&ssum[ocl], s);
        atomicAdd(&ssq[ocl], q);
        __syncthreads();
        if (tid < 64) {
            atomicAdd(&g_sum[oc0 + tid], ssum[tid]);
            atomicAdd(&g_sumsq[oc0 + tid], ssq[tid]);
        }
    }

    __syncthreads();
#pragma unroll
    for (int u = 0; u < 16; u++) o_s[ocl][tbase + u] = acc[u];
    __syncthreads();
    float* ob = out + ((size_t)b * TS_INT + t0) * ND + oc0;
    for (int idx = tid; idx < 4096; idx += 256) {
        int t = idx >> 6, oc = idx & 63;
        if (t0 + t < Lout) ob[(size_t)t * ND + oc] = o_s[oc][t];
    }
}

// ---------------- BN stats -> scale/shift for next layer; resets stats ----------
__global__ void scaleshift_kernel(const float* __restrict__ g, const float* __restrict__ be, double N)
{
    int c = threadIdx.x;
    double m = g_sum[c] / N;
    double var = g_sumsq[c] / N - m * m;
    double r = 1.0 / sqrt(var + 1e-5);
    double sc = (double)g[c] * r;
    g_scale[c] = (float)sc;
    g_shift[c] = (float)((double)be[c] - m * sc);
    g_sum[c] = 0.0;
    g_sumsq[c] = 0.0;
}

// ---------------- ||codebook_k||^2 (exact fp32) ---------------------------------
__global__ void cnorm_kernel(const float* __restrict__ cb)
{
    int gw = (blockIdx.x * 256 + threadIdx.x) >> 5;
    int lane = threadIdx.x & 31;
    float s = 0.f;
    const float* row = cb + (size_t)gw * ND;
    for (int d = lane; d < ND; d += 32) { float v = row[d]; s = fmaf(v, v, s); }
#pragma unroll
    for (int off = 16; off; off >>= 1) s += __shfl_xor_sync(0xffffffffu, s, off);
    if (lane == 0) g_cnorm[gw] = s;
}

// ============ VQ argmin as mma.sync tf32 3x-split GEMM (src=g_zhi/lo) ===========
__global__ __launch_bounds__(256, 1) void vqmma_kernel(int* __restrict__ ids)
{
    extern __shared__ __align__(1024) char smem[];
    const int tid = threadIdx.x;
    const int wid = tid >> 5, lane = tid & 31;
    const int tok0 = blockIdx.x * 64;
    const int tokw = (wid >> 2) * 32;
    const int cw = (wid & 3) * 16;

    const uint32_t sb = smem_u32(smem);

    {
        const float* zhi = g_zhi;
        const float* zlo = g_zlo;
#pragma unroll
        for (int it = 0; it < 32; it++) {
            int idx = tid + it * 256;
            int q = idx & 7, r = (idx >> 3) & 63, kc = (idx >> 9) & 7, half = idx >> 12;
            const float* src = (half ? zlo : zhi) + ((size_t)(tok0 + r) * 256 + kc * 32 + q * 4);
            uint32_t dst = sb + half * VQ_ZLO + kc * 8192 + swz((uint32_t)(r * 128 + q * 16));
            CP_ASYNC16(dst, src);
        }
        CP_COMMIT();
    }
    {
#pragma unroll
        for (int it = 0; it < 4; it++) {
            int idx = tid + it * 256;
            int q = idx & 7, r = (idx >> 3) & 63, half = idx >> 9;
            const float* src = (half ? g_wlo : g_whi) + ((size_t)r * 256 + q * 4);
            uint32_t dst = sb + VQ_B + half * 8192 + swz((uint32_t)(r * 128 + q * 16));
            CP_ASYNC16(dst, src);
        }
        CP_COMMIT();
    }

    uint32_t abase[2];
    {
        int ar = tokw + (lane & 7) + ((lane >> 3) & 1) * 8;
        int aq = (lane >> 4) & 1;
#pragma unroll
        for (int mt = 0; mt < 2; mt++) {
            int r = ar + mt * 16;
            abase[mt] = (uint32_t)(r * 128 + ((aq * 16) ^ ((r & 7) << 4)));
        }
    }
    const int brow = cw + (lane & 7) + (((lane >> 4) & 1) << 3);
    const uint32_t bcol = (uint32_t)(((lane >> 3) & 1) << 4);

    unsigned long long best[4];
#pragma unroll
    for (int i = 0; i < 4; i++) best[i] = ~0ull;

    float C[2][2][4];

    for (int s = 0; s < 128; s++) {
        const int ct = s >> 3, kc = s & 7;
        const uint32_t bst = sb + VQ_B + (s & 1) * VQ_BST;

        CP_WAIT0();
        __syncthreads();

        if (s + 1 < 128) {
            const int nct = (s + 1) >> 3, nkc = (s + 1) & 7;
            uint32_t sd = sb + VQ_B + ((s + 1) & 1) * VQ_BST;
#pragma unroll
            for (int it = 0; it < 4; it++) {
                int idx = tid + it * 256;
                int q = idx & 7, r = (idx >> 3) & 63, half = idx >> 9;
                const float* src = (half ? g_wlo : g_whi) + ((size_t)(nct * 64 + r) * 256 + nkc * 32 + q * 4);
                uint32_t dst = sd + half * 8192 + swz((uint32_t)(r * 128 + q * 16));
                CP_ASYNC16(dst, src);
            }
            CP_COMMIT();
        }

        if (kc == 0) {
#pragma unroll
            for (int mt = 0; mt < 2; mt++)
#pragma unroll
                for (int nt = 0; nt < 2; nt++)
#pragma unroll
                    for (int q = 0; q < 4; q++) C[mt][nt][q] = 0.f;
        }

        const uint32_t za = sb + kc * 8192;
#pragma unroll
        for (int ks = 0; ks < 4; ks++) {
            uint32_t bh[2][2], bl[2][2], ah[2][4], al[2][4];
            {
                uint32_t byte = (uint32_t)(brow * 128) + (((uint32_t)(ks * 32) + bcol) ^ ((uint32_t)(brow & 7) << 4));
                uint32_t ad = bst + byte;
                ldm_x4(bh[0][0], bh[0][1], bh[1][0], bh[1][1], ad);
                ldm_x4(bl[0][0], bl[0][1], bl[1][0], bl[1][1], ad + 8192);
            }
#pragma unroll
            for (int mt = 0; mt < 2; mt++) {
                uint32_t ad = za + (abase[mt] ^ (uint32_t)(ks << 5));
                ldm_x4(ah[mt][0], ah[mt][1], ah[mt][2], ah[mt][3], ad);
            }
#pragma unroll
            for (int mt = 0; mt < 2; mt++)
#pragma unroll
                for (int nt = 0; nt < 2; nt++) mma8(C[mt][nt], ah[mt], bh[nt]);
#pragma unroll
            for (int mt = 0; mt < 2; mt++)
#pragma unroll
                for (int nt = 0; nt < 2; nt++) mma8(C[mt][nt], ah[mt], bl[nt]);
#pragma unroll
            for (int mt = 0; mt < 2; mt++) {
                uint32_t ad = za + VQ_ZLO + (abase[mt] ^ (uint32_t)(ks << 5));
                ldm_x4(al[mt][0], al[mt][1], al[mt][2], al[mt][3], ad);
            }
#pragma unroll
            for (int mt = 0; mt < 2; mt++)
#pragma unroll
                for (int nt = 0; nt < 2; nt++) mma8(C[mt][nt], al[mt], bh[nt]);
        }

        if (kc == 7) {
#pragma unroll
            for (int mt = 0; mt < 2; mt++)
#pragma unroll
                for (int h = 0; h < 2; h++) {
#pragma unroll
                    for (int nt = 0; nt < 2; nt++)
#pragma unroll
                        for (int p = 0; p < 2; p++) {
                            int code = ct * 64 + cw + nt * 8 + (lane & 3) * 2 + p;
                            float dist = fmaf(-2.f, C[mt][nt][h * 2 + p], g_cnorm[code]);
                            unsigned long long cand =
                                ((unsigned long long)fbits_ord(dist) << 32) | (unsigned)code;
                            unsigned long long* bp = &best[mt * 2 + h];
                            if (cand < *bp) *bp = cand;
                        }
                }
        }
    }

#pragma unroll
    for (int off = 1; off <= 2; off <<= 1) {
#pragma unroll
        for (int i = 0; i < 4; i++) {
            unsigned long long o = __shfl_xor_sync(0xffffffffu, best[i], off);
            if (o < best[i]) best[i] = o;
        }
    }
    unsigned long long* red = (unsigned long long*)(smem + VQ_RED);   // [64][4]
    __syncthreads();
    if ((lane & 3) == 0) {
#pragma unroll
        for (int mt = 0; mt < 2; mt++)
#pragma unroll
            for (int h = 0; h < 2; h++) {
                int trow = tokw + mt * 16 + h * 8 + (lane >> 2);
                red[trow * 4 + (wid & 3)] = best[mt * 2 + h];
            }
    }
    __syncthreads();
    if (tid < 64) {
        unsigned long long m = red[tid * 4];
#pragma unroll
        for (int i = 1; i < 4; i++) { unsigned long long o = red[tid * 4 + i]; if (o < m) m = o; }
        ids[tok0 + tid] = (int)(m & 0xFFFFFFFFu);
    }
}

// ---------------- VQ tail: counts + z_q + segment sums --------------------------
__global__ __launch_bounds__(256) void vqtail_kernel(
    const float* __restrict__ ze, const float* __restrict__ cb, float* __restrict__ zq)
{
    __shared__ int sid[64];
    const int tid = threadIdx.x;
    const int tok0 = blockIdx.x * 64;
    if (tid < 64) sid[tid] = g_ids[tok0 + tid];
    __syncthreads();
    if (tid < 64) atomicAdd(&g_cnt[sid[tid]], 1.0f);
    for (int e = tid; e < 64 * ND; e += 256) {
        int r = e >> 8, d = e & 255;
        int code = sid[r];
        size_t gz = (size_t)(tok0 + r) * ND + d;
        float zev = ze[gz];
        float cbv = cb[(size_t)code * ND + d];
        zq[gz] = zev + (cbv - zev);
        atomicAdd(&g_sumcur[(size_t)code * ND + d], zev);
    }
}

// ---------------- EMA epilogue ---------------------------------------------------
__global__ void ema1_kernel(const float* __restrict__ ecs, float* __restrict__ necs)
{
    __shared__ float red[1024];
    int k = threadIdx.x;
    float ne = ecs[k] * 0.99f + 0.01f * g_cnt[k];
    necs[k] = ne;
    g_cnt[k] = 0.f;
    red[k] = ne;
    __syncthreads();
    for (int off = 512; off; off >>= 1) {
        if (k < off) red[k] += red[k + off];
        __syncthreads();
    }
    if (k == 0) g_n = red[0];
}

__global__ void ema2_kernel(const float* __restrict__ ema_w, const float* __restrict__ necs,
                            float* __restrict__ ncb)
{
    int k = blockIdx.x, d = threadIdx.x;
    float n = g_n;
    float smoothed = (necs[k] + 1e-5f) / (n + 1024.f * 1e-5f) * n;
    size_t idx = (size_t)k * ND + d;
    float nw = ema_w[idx] * 0.99f + 0.01f * g_sumcur[idx];
    ncb[idx] = nw / smoothed;
    g_sumcur[idx] = 0.f;
}

// ---------------- host launcher ---------------------------------------------------
extern "C" void kernel_launch(void* const* d_in, const int* in_sizes, int n_in,
                              void* d_out, int out_size)
{
    const float* X = (const float*)d_in[0];
    const float *W[6], *Bi[6], *G[5], *Be[5];

    bool sig = (in_sizes[3] == 256);
    if (!sig) {
        for (int i = 0; i < 6; i++) { W[i] = (const float*)d_in[1 + 2 * i]; Bi[i] = (const float*)d_in[2 + 2 * i]; }
        for (int i = 0; i < 5; i++) { G[i] = (const float*)d_in[13 + 2 * i]; Be[i] = (const float*)d_in[14 + 2 * i]; }
    } else {
        for (int i = 0; i < 5; i++) {
            W[i]  = (const float*)d_in[1 + 4 * i];
            Bi[i] = (const float*)d_in[2 + 4 * i];
            G[i]  = (const float*)d_in[3 + 4 * i];
            Be[i] = (const float*)d_in[4 + 4 * i];
        }
        W[5] = (const float*)d_in[21];
        Bi[5] = (const float*)d_in[22];
    }
    const float* codebook = (const float*)d_in[23];
    const float* ema_w    = (const float*)d_in[24];
    const float* ecs      = (const float*)d_in[25];

    float* out  = (float*)d_out;
    float* ze   = out;
    float* zq   = out + (size_t)33554432;
    float* ncb  = out + (size_t)67108864;
    float* necs = out + (size_t)67371008;

    float *bufA = nullptr, *bufB = nullptr, *wsp = nullptr;
    cudaGetSymbolAddress((void**)&bufA, g_bufA);
    cudaGetSymbolAddress((void**)&bufB, g_bufB);
    cudaGetSymbolAddress((void**)&wsp, g_wsp);
    int* idsp = nullptr;
    cudaGetSymbolAddress((void**)&idsp, g_ids);

    cudaFuncSetAttribute(convmma_kernel, cudaFuncAttributeMaxDynamicSharedMemorySize, SMEM_MMA);
    cudaFuncSetAttribute(vqmma_kernel, cudaFuncAttributeMaxDynamicSharedMemorySize, SMEM_VQ);

    const size_t LSLICE = (size_t)2 * ND * 1024;   // floats per layer slice

    dim3 blk(256);
    dim3 cblk(128);
    // one-shot weight splits for all 5 D->D layers (parallel, off critical path)
    wsplit_all_kernel<<<dim3(256, 5), blk>>>(W[1], W[2], W[3], W[4], W[5]);
    conv1_kernel<<<dim3(65, 4, 32), blk>>>(X, W[0], Bi[0], bufA);
    scaleshift_kernel<<<1, 256>>>(G[0], Be[0], (double)(32.0 * 4097.0));
    convmma_kernel<<<dim3(64, 4, 32), cblk, SMEM_MMA>>>(bufA, wsp + 0 * LSLICE, Bi[1], bufB, 4097, 4096, 1, TS_INT, 1, 0);
    scaleshift_kernel<<<1, 256>>>(G[1], Be[1], (double)(32.0 * 4096.0));
    convmma_kernel<<<dim3(65, 4, 32), cblk, SMEM_MMA>>>(bufB, wsp + 1 * LSLICE, Bi[2], bufA, 4096, 4097, 2, TS_INT, 1, 0);
    scaleshift_kernel<<<1, 256>>>(G[2], Be[2], (double)(32.0 * 4097.0));
    convmma_kernel<<<dim3(64, 4, 32), cblk, SMEM_MMA>>>(bufA, wsp + 2 * LSLICE, Bi[3], bufB, 4097, 4096, 1, TS_INT, 1, 0);
    scaleshift_kernel<<<1, 256>>>(G[3], Be[3], (double)(32.0 * 4096.0));
    convmma_kernel<<<dim3(65, 4, 32), cblk, SMEM_MMA>>>(bufB, wsp + 3 * LSLICE, Bi[4], bufA, 4096, 4097, 2, TS_INT, 1, 0);
    scaleshift_kernel<<<1, 256>>>(G[4], Be[4], (double)(32.0 * 4097.0));
    // L6: writes z_e AND its tf32 hi/lo split (fused)
    convmma_kernel<<<dim3(64, 4, 32), cblk, SMEM_MMA>>>(bufA, wsp + 4 * LSLICE, Bi[5], ze, 4097, 4096, 1, 4096, 0, 1);

    csplit_kernel<<<256, 256>>>(codebook);
    cnorm_kernel<<<128, 256>>>(codebook);
    vqmma_kernel<<<2048, 256, SMEM_VQ>>>(idsp);
    vqtail_kernel<<<2048, 256>>>(ze, codebook, zq);
    ema1_kernel<<<1, 1024>>>(ecs, necs);
    ema2_kernel<<<1024, 256>>>(ema_w, necs, ncb);
}